// round 3
// baseline (speedup 1.0000x reference)
#include <cuda_runtime.h>
#include <math.h>

#define Bb 8
#define Hh 12
#define Nn 2048
#define Dm 768
#define HD 64
#define Mf 256
#define BH (Bb*Hh)

#define DN    0.35355339059327373f  /* 64^-0.25 */
#define RATIO 0.0625f               /* 256^-0.5 */
#define EPSV  1e-4f

// ---------------- scratch (static device globals; no allocs allowed) ---------
__device__ float g_q[BH*Nn*HD];
__device__ float g_k[BH*Nn*HD];
__device__ float g_v[BH*Nn*HD];
__device__ float g_qp[BH*Nn*Mf];
__device__ float g_kp[BH*Nn*Mf];
__device__ float g_kmax[BH];
__device__ float g_ksum[BH*Mf];
__device__ float g_ctx[BH*Mf*HD];
__device__ float g_attn[Bb*Nn*Dm];
__device__ float g_projT[HD*Mf];

__device__ __forceinline__ void atomicMaxFloat(float* addr, float val) {
    if (val >= 0.f) atomicMax((int*)addr, __float_as_int(val));
    else            atomicMin((unsigned int*)addr, __float_as_uint(val));
}

// ---------------- init: zero accumulators, -inf maxes, transpose proj --------
__global__ void init_kernel(const float* __restrict__ proj) {
    int i = blockIdx.x * blockDim.x + threadIdx.x;
    int stride = gridDim.x * blockDim.x;
    for (int j = i; j < BH*Mf*HD; j += stride) g_ctx[j] = 0.f;
    if (i < BH*Mf) g_ksum[i] = 0.f;
    if (i < BH)    g_kmax[i] = -INFINITY;
    if (i < Mf*HD) {
        int m = i >> 6, d = i & 63;
        g_projT[d*Mf + m] = proj[i];
    }
}

// ---------------- NT GEMM: C[M,768] = A[M,768] @ W[768,768]^T + bias ---------
// MODE 0/1/2: scatter store to g_q/g_k/g_v as [b][h][n][64]. MODE 3: plain store.
template<int MODE>
__global__ __launch_bounds__(256) void gemm_nt(const float* __restrict__ A,
                                               const float* __restrict__ W,
                                               const float* __restrict__ bias,
                                               float* __restrict__ Cout) {
    __shared__ float As[8][128];
    __shared__ float Bs[8][128];
    const int tid = threadIdx.x;
    const int m0 = blockIdx.y * 128, n0 = blockIdx.x * 128;
    const int lrow = tid >> 1, lk4 = (tid & 1) * 4;
    const float* Ain = (MODE == 3) ? g_attn : A;
    const float* Ap = Ain + (size_t)(m0 + lrow) * Dm + lk4;
    const float* Wp = W   + (size_t)(n0 + lrow) * Dm + lk4;
    const int ty = tid >> 4, tx = tid & 15;

    float acc[8][8];
#pragma unroll
    for (int i = 0; i < 8; i++)
#pragma unroll
        for (int j = 0; j < 8; j++) acc[i][j] = 0.f;

    for (int k0 = 0; k0 < Dm; k0 += 8) {
        float4 a = *(const float4*)(Ap + k0);
        float4 w = *(const float4*)(Wp + k0);
        __syncthreads();
        As[lk4+0][lrow] = a.x; As[lk4+1][lrow] = a.y;
        As[lk4+2][lrow] = a.z; As[lk4+3][lrow] = a.w;
        Bs[lk4+0][lrow] = w.x; Bs[lk4+1][lrow] = w.y;
        Bs[lk4+2][lrow] = w.z; Bs[lk4+3][lrow] = w.w;
        __syncthreads();
#pragma unroll
        for (int kk = 0; kk < 8; kk++) {
            float af[8], bf[8];
            *(float4*)&af[0] = *(const float4*)&As[kk][ty*4];
            *(float4*)&af[4] = *(const float4*)&As[kk][64 + ty*4];
            *(float4*)&bf[0] = *(const float4*)&Bs[kk][tx*4];
            *(float4*)&bf[4] = *(const float4*)&Bs[kk][64 + tx*4];
#pragma unroll
            for (int i = 0; i < 8; i++)
#pragma unroll
                for (int j = 0; j < 8; j++) acc[i][j] += af[i] * bf[j];
        }
    }

#pragma unroll
    for (int i = 0; i < 8; i++) {
        int row = (i < 4) ? (ty*4 + i) : (64 + ty*4 + (i - 4));
        int m = m0 + row;
#pragma unroll
        for (int jg = 0; jg < 2; jg++) {
            int c0 = n0 + jg*64 + tx*4;
            float4 bb = *(const float4*)(bias + c0);
            float4 v;
            v.x = acc[i][jg*4+0] + bb.x;
            v.y = acc[i][jg*4+1] + bb.y;
            v.z = acc[i][jg*4+2] + bb.z;
            v.w = acc[i][jg*4+3] + bb.w;
            if (MODE == 3) {
                *(float4*)(Cout + (size_t)m*Dm + c0) = v;
            } else {
                int b = m >> 11, n = m & 2047, h = c0 >> 6, dd = c0 & 63;
                float* dst = (MODE == 0) ? g_q : (MODE == 1) ? g_k : g_v;
                *(float4*)(dst + (size_t)(((b*Hh + h)*Nn + n) << 6) + dd) = v;
            }
        }
    }
}

// ---------------- FAVOR+ feature maps ----------------------------------------
// Each warp handles 8 rows of one (b,h). xp = DN * (x . proj[m]), diag = 0.0625*|x|^2.
// ISQ=1: per-row max, full exp epilogue into g_qp.
// ISQ=0: store (xp - diag) raw into g_kp, block-reduce raw-xp max -> atomicMax g_kmax.
template<int ISQ>
__global__ __launch_bounds__(256) void feat_kernel() {
    const int bh = blockIdx.x;
    const int warp = threadIdx.x >> 5, lane = threadIdx.x & 31;
    const int nbase = blockIdx.y * 64 + warp * 8;
    __shared__ float shq[8][8][64];
    __shared__ float smax[8];

    const float* src = (ISQ ? g_q : g_k) + (size_t)((bh*Nn + nbase) << 6);
#pragma unroll
    for (int i = 0; i < 4; i++) {
        int fi = i*32 + lane;                    // float4 index within 512 floats
        float4 v = ((const float4*)src)[fi];
        *(float4*)&shq[warp][fi >> 4][(fi & 15) * 4] = v;
    }
    __syncwarp();

    float diag[8];
#pragma unroll
    for (int r = 0; r < 8; r++) {
        float a = shq[warp][r][lane], b = shq[warp][r][lane + 32];
        float p = a*a + b*b;
#pragma unroll
        for (int o = 16; o > 0; o >>= 1) p += __shfl_xor_sync(0xffffffffu, p, o);
        diag[r] = p * 0.0625f;                   // 0.5 * 64^-0.5
    }

    float acc[8][8];
#pragma unroll
    for (int r = 0; r < 8; r++)
#pragma unroll
        for (int s = 0; s < 8; s++) acc[r][s] = 0.f;

    const float4* pT = (const float4*)g_projT;
#pragma unroll 4
    for (int d = 0; d < 64; d++) {
        float4 p0 = pT[d*64 + lane];
        float4 p1 = pT[d*64 + 32 + lane];
#pragma unroll
        for (int r = 0; r < 8; r++) {
            float qd = shq[warp][r][d];
            acc[r][0] += qd*p0.x; acc[r][1] += qd*p0.y;
            acc[r][2] += qd*p0.z; acc[r][3] += qd*p0.w;
            acc[r][4] += qd*p1.x; acc[r][5] += qd*p1.y;
            acc[r][6] += qd*p1.z; acc[r][7] += qd*p1.w;
        }
    }

    if (ISQ) {
#pragma unroll
        for (int r = 0; r < 8; r++) {
            float xv[8]; float mx = -INFINITY;
#pragma unroll
            for (int s = 0; s < 8; s++) { xv[s] = acc[r][s] * DN; mx = fmaxf(mx, xv[s]); }
#pragma unroll
            for (int o = 16; o > 0; o >>= 1) mx = fmaxf(mx, __shfl_xor_sync(0xffffffffu, mx, o));
            float base = diag[r] + mx;
            float* op = g_qp + (size_t)(bh*Nn + nbase + r) * Mf;
            float4 o0, o1;
            o0.x = RATIO*(__expf(xv[0]-base)+EPSV); o0.y = RATIO*(__expf(xv[1]-base)+EPSV);
            o0.z = RATIO*(__expf(xv[2]-base)+EPSV); o0.w = RATIO*(__expf(xv[3]-base)+EPSV);
            o1.x = RATIO*(__expf(xv[4]-base)+EPSV); o1.y = RATIO*(__expf(xv[5]-base)+EPSV);
            o1.z = RATIO*(__expf(xv[6]-base)+EPSV); o1.w = RATIO*(__expf(xv[7]-base)+EPSV);
            ((float4*)op)[lane]      = o0;   // m = lane*4 .. +3
            ((float4*)op)[32 + lane] = o1;   // m = 128 + lane*4 .. +3
        }
    } else {
        float wmax = -INFINITY;
#pragma unroll
        for (int r = 0; r < 8; r++) {
            float dg = diag[r];
            float xv[8];
#pragma unroll
            for (int s = 0; s < 8; s++) { xv[s] = acc[r][s] * DN; wmax = fmaxf(wmax, xv[s]); }
            float* op = g_kp + (size_t)(bh*Nn + nbase + r) * Mf;
            float4 o0, o1;
            o0.x = xv[0]-dg; o0.y = xv[1]-dg; o0.z = xv[2]-dg; o0.w = xv[3]-dg;
            o1.x = xv[4]-dg; o1.y = xv[5]-dg; o1.z = xv[6]-dg; o1.w = xv[7]-dg;
            ((float4*)op)[lane]      = o0;
            ((float4*)op)[32 + lane] = o1;
        }
#pragma unroll
        for (int o = 16; o > 0; o >>= 1) wmax = fmaxf(wmax, __shfl_xor_sync(0xffffffffu, wmax, o));
        if (lane == 0) smax[warp] = wmax;
        __syncthreads();
        if (threadIdx.x == 0) {
            float m = smax[0];
#pragma unroll
            for (int w = 1; w < 8; w++) m = fmaxf(m, smax[w]);
            atomicMaxFloat(&g_kmax[bh], m);
        }
    }
}

// ---------------- K exp pass + k_sum -----------------------------------------
__global__ __launch_bounds__(256) void featk_exp_kernel() {
    const int bh = blockIdx.x;
    const int n0 = blockIdx.y * 256;
    const int m = threadIdx.x;
    const float kmax = g_kmax[bh];
    float s = 0.f;
    float* base = g_kp + (size_t)(bh*Nn + n0) * Mf + m;
#pragma unroll 4
    for (int i = 0; i < 256; i++) {
        float y = base[(size_t)i * Mf];
        float e = RATIO * (__expf(y - kmax) + EPSV);
        base[(size_t)i * Mf] = e;
        s += e;
    }
    atomicAdd(&g_ksum[bh*Mf + m], s);
}

// ---------------- ctx = kp^T @ v per (b,h): [256 x 64] ------------------------
__global__ __launch_bounds__(256) void ctx_kernel() {
    const int bh = blockIdx.x;
    const int nbase = blockIdx.y * 256;   // 8 splits of n
    __shared__ float ks_[16][256];
    __shared__ float vs[16][64];
    const int tid = threadIdx.x;
    const int tm = tid & 31, td = tid >> 5;

    float acc[8][8];
#pragma unroll
    for (int i = 0; i < 8; i++)
#pragma unroll
        for (int j = 0; j < 8; j++) acc[i][j] = 0.f;

    for (int t = 0; t < 16; t++) {
        int nb = nbase + t * 16;
        __syncthreads();
#pragma unroll
        for (int q = 0; q < 4; q++) {
            int t4 = tid + q*256;
            int r = t4 >> 6, c4 = (t4 & 63) * 4;
            *(float4*)&ks_[r][c4] = *(const float4*)(g_kp + (size_t)(bh*Nn + nb + r)*Mf + c4);
        }
        {
            int r = tid >> 4, c4 = (tid & 15) * 4;
            *(float4*)&vs[r][c4] = *(const float4*)(g_v + (size_t)((bh*Nn + nb + r) << 6) + c4);
        }
        __syncthreads();
#pragma unroll
        for (int i = 0; i < 16; i++) {
            float b0[8];
            *(float4*)&b0[0] = *(const float4*)&vs[i][td*8];
            *(float4*)&b0[4] = *(const float4*)&vs[i][td*8 + 4];
#pragma unroll
            for (int mi = 0; mi < 8; mi++) {
                float a = ks_[i][tm + 32*mi];
#pragma unroll
                for (int di = 0; di < 8; di++) acc[mi][di] += a * b0[di];
            }
        }
    }
#pragma unroll
    for (int mi = 0; mi < 8; mi++) {
        int m = tm + 32*mi;
#pragma unroll
        for (int di = 0; di < 8; di++)
            atomicAdd(&g_ctx[(size_t)(bh*Mf + m)*HD + td*8 + di], acc[mi][di]);
    }
}

// ---------------- out = (qp @ ctx) * 1/(qp @ ksum), store [b][n][h*64+dd] -----
__global__ __launch_bounds__(256) void attn_out_kernel() {
    const int bh = blockIdx.x;
    const int n0 = blockIdx.y * 128;
    __shared__ float qs[8][128];
    __shared__ float cs[8][64];
    __shared__ float ksm[8];
    const int tid = threadIdx.x;
    const int ty = tid >> 4, tx = tid & 15;

    float acc[8][4]; float dp[8];
#pragma unroll
    for (int i = 0; i < 8; i++) {
        dp[i] = 0.f;
#pragma unroll
        for (int j = 0; j < 4; j++) acc[i][j] = 0.f;
    }

    for (int mt = 0; mt < 32; mt++) {
        int m0 = mt * 8;
        __syncthreads();
        {
            int row = tid >> 1, k4 = (tid & 1) * 4;
            float4 v = *(const float4*)(g_qp + (size_t)(bh*Nn + n0 + row)*Mf + m0 + k4);
            qs[k4+0][row] = v.x; qs[k4+1][row] = v.y;
            qs[k4+2][row] = v.z; qs[k4+3][row] = v.w;
        }
        if (tid < 128) {
            int kr = tid >> 4, c4 = (tid & 15) * 4;
            *(float4*)&cs[kr][c4] = *(const float4*)(g_ctx + (size_t)(bh*Mf + m0 + kr)*HD + c4);
        }
        if (tid < 8) ksm[tid] = g_ksum[bh*Mf + m0 + tid];
        __syncthreads();
#pragma unroll
        for (int kk = 0; kk < 8; kk++) {
            float af[8];
            *(float4*)&af[0] = *(const float4*)&qs[kk][ty*4];
            *(float4*)&af[4] = *(const float4*)&qs[kk][64 + ty*4];
            float4 b = *(const float4*)&cs[kk][tx*4];
            float kv = ksm[kk];
#pragma unroll
            for (int i = 0; i < 8; i++) {
                dp[i] += af[i] * kv;
                acc[i][0] += af[i]*b.x; acc[i][1] += af[i]*b.y;
                acc[i][2] += af[i]*b.z; acc[i][3] += af[i]*b.w;
            }
        }
    }

    const int b_ = bh / Hh, h = bh % Hh;
#pragma unroll
    for (int i = 0; i < 8; i++) {
        int row = (i < 4) ? (ty*4 + i) : (64 + ty*4 + (i - 4));
        int n = n0 + row;
        float dinv = 1.0f / dp[i];
        float4 v;
        v.x = acc[i][0]*dinv; v.y = acc[i][1]*dinv;
        v.z = acc[i][2]*dinv; v.w = acc[i][3]*dinv;
        *(float4*)(g_attn + (size_t)(b_*Nn + n)*Dm + h*64 + tx*4) = v;
    }
}

// ---------------- launch ------------------------------------------------------
extern "C" void kernel_launch(void* const* d_in, const int* in_sizes, int n_in,
                              void* d_out, int out_size) {
    const float* x    = (const float*)d_in[0];
    const float* Wq   = (const float*)d_in[1];
    const float* bq   = (const float*)d_in[2];
    const float* Wk   = (const float*)d_in[3];
    const float* bk   = (const float*)d_in[4];
    const float* Wv   = (const float*)d_in[5];
    const float* bv   = (const float*)d_in[6];
    const float* Wo   = (const float*)d_in[7];
    const float* bo   = (const float*)d_in[8];
    const float* proj = (const float*)d_in[9];
    float* out = (float*)d_out;

    init_kernel<<<6144, 256>>>(proj);

    dim3 gg(Dm/128, (Bb*Nn)/128);           // (6, 128)
    gemm_nt<0><<<gg, 256>>>(x, Wq, bq, nullptr);
    gemm_nt<1><<<gg, 256>>>(x, Wk, bk, nullptr);
    gemm_nt<2><<<gg, 256>>>(x, Wv, bv, nullptr);

    feat_kernel<1><<<dim3(BH, Nn/64), 256>>>();   // qp
    feat_kernel<0><<<dim3(BH, Nn/64), 256>>>();   // kp raw + kmax
    featk_exp_kernel<<<dim3(BH, 8), 256>>>();     // kp exp + ksum

    ctx_kernel<<<dim3(BH, 8), 256>>>();
    attn_out_kernel<<<dim3(BH, Nn/128), 256>>>();

    gemm_nt<3><<<gg, 256>>>(nullptr, Wo, bo, out);
}

// round 5
// speedup vs baseline: 1.1168x; 1.1168x over previous
#include <cuda_runtime.h>
#include <math.h>

#define Bb 8
#define Hh 12
#define Nn 2048
#define Dm 768
#define HD 64
#define Mf 256
#define BH (Bb*Hh)

#define DN    0.35355339059327373f  /* 64^-0.25 */
#define RATIO 0.0625f               /* 256^-0.5 */
#define EPSV  1e-4f

typedef unsigned long long u64;

// ---------------- packed f32x2 helpers (FFMA2 path, sm_103a) -----------------
__device__ __forceinline__ u64 pk2(float lo, float hi) {
    u64 r; asm("mov.b64 %0, {%1, %2};" : "=l"(r) : "f"(lo), "f"(hi)); return r;
}
__device__ __forceinline__ u64 dupf(float v) {
    u64 r; asm("mov.b64 %0, {%1, %1};" : "=l"(r) : "f"(v)); return r;
}
__device__ __forceinline__ void fma2(u64& d, u64 a, u64 b) {
    asm("fma.rn.f32x2 %0, %1, %2, %0;" : "+l"(d) : "l"(a), "l"(b));
}
__device__ __forceinline__ float2 up2(u64 v) {
    float2 f; asm("mov.b64 {%0, %1}, %2;" : "=f"(f.x), "=f"(f.y) : "l"(v)); return f;
}

// ---------------- scratch (static device globals; no allocs allowed) ---------
__device__ float g_q[BH*Nn*HD];
__device__ float g_k[BH*Nn*HD];
__device__ float g_v[BH*Nn*HD];
__device__ float g_qp[BH*Nn*Mf];
__device__ float g_kp[BH*Nn*Mf];
__device__ float g_kmax[BH];
__device__ float g_ksum[BH*Mf];
__device__ float g_ctx[BH*Mf*HD];
__device__ float g_attn[Bb*Nn*Dm];
__device__ float g_projT[HD*Mf];

__device__ __forceinline__ void atomicMaxFloat(float* addr, float val) {
    if (val >= 0.f) atomicMax((int*)addr, __float_as_int(val));
    else            atomicMin((unsigned int*)addr, __float_as_uint(val));
}

// ---------------- init: zero accumulators, -inf maxes, transpose proj --------
__global__ void init_kernel(const float* __restrict__ proj) {
    int i = blockIdx.x * blockDim.x + threadIdx.x;
    int stride = gridDim.x * blockDim.x;
    for (int j = i; j < BH*Mf*HD; j += stride) g_ctx[j] = 0.f;
    if (i < BH*Mf) g_ksum[i] = 0.f;
    if (i < BH)    g_kmax[i] = -INFINITY;
    if (i < Mf*HD) {
        int m = i >> 6, d = i & 63;
        g_projT[d*Mf + m] = proj[i];
    }
}

// ---------------- NT GEMM: C[M,768] = A[M,768] @ W[768,768]^T + bias ---------
// FFMA2 inner micro-kernel; global->reg prefetch hides LDG behind compute.
// MODE 0/1/2: scatter store to g_q/g_k/g_v as [b][h][n][64]. MODE 3: plain store.
template<int MODE>
__global__ __launch_bounds__(256) void gemm_nt(const float* __restrict__ A,
                                               const float* __restrict__ W,
                                               const float* __restrict__ bias,
                                               float* __restrict__ Cout) {
    __shared__ float As[8][128];
    __shared__ float Bs[8][128];
    const int tid = threadIdx.x;
    const int m0 = blockIdx.y * 128, n0 = blockIdx.x * 128;
    const int lrow = tid >> 1, lk4 = (tid & 1) * 4;
    const float* Ain = (MODE == 3) ? g_attn : A;
    const float* Ap = Ain + (size_t)(m0 + lrow) * Dm + lk4;
    const float* Wp = W   + (size_t)(n0 + lrow) * Dm + lk4;
    const int ty = tid >> 4, tx = tid & 15;

    // acc2[ip][j]: row-pair ip (2 rows packed in f32x2), col j (8 cols)
    u64 acc2[4][8];
#pragma unroll
    for (int i = 0; i < 4; i++)
#pragma unroll
        for (int j = 0; j < 8; j++) acc2[i][j] = 0ULL;

    float4 a_nx = *(const float4*)(Ap);
    float4 w_nx = *(const float4*)(Wp);

    for (int k0 = 0; k0 < Dm; k0 += 8) {
        __syncthreads();
        As[lk4+0][lrow] = a_nx.x; As[lk4+1][lrow] = a_nx.y;
        As[lk4+2][lrow] = a_nx.z; As[lk4+3][lrow] = a_nx.w;
        Bs[lk4+0][lrow] = w_nx.x; Bs[lk4+1][lrow] = w_nx.y;
        Bs[lk4+2][lrow] = w_nx.z; Bs[lk4+3][lrow] = w_nx.w;
        __syncthreads();
        if (k0 + 8 < Dm) {
            a_nx = *(const float4*)(Ap + k0 + 8);
            w_nx = *(const float4*)(Wp + k0 + 8);
        }
#pragma unroll
        for (int kk = 0; kk < 8; kk++) {
            float4 a0 = *(const float4*)&As[kk][ty*4];
            float4 a1 = *(const float4*)&As[kk][64 + ty*4];
            float4 b0 = *(const float4*)&Bs[kk][tx*4];
            float4 b1 = *(const float4*)&Bs[kk][64 + tx*4];
            u64 ap[4] = { pk2(a0.x,a0.y), pk2(a0.z,a0.w),
                          pk2(a1.x,a1.y), pk2(a1.z,a1.w) };
            u64 bd[8] = { dupf(b0.x), dupf(b0.y), dupf(b0.z), dupf(b0.w),
                          dupf(b1.x), dupf(b1.y), dupf(b1.z), dupf(b1.w) };
#pragma unroll
            for (int ip = 0; ip < 4; ip++)
#pragma unroll
                for (int j = 0; j < 8; j++) fma2(acc2[ip][j], ap[ip], bd[j]);
        }
    }

#pragma unroll
    for (int ip = 0; ip < 4; ip++) {
        int rbase = (ip < 2) ? (ty*4 + ip*2) : (64 + ty*4 + (ip-2)*2);
#pragma unroll
        for (int jg = 0; jg < 2; jg++) {
            float2 c0 = up2(acc2[ip][jg*4+0]);
            float2 c1 = up2(acc2[ip][jg*4+1]);
            float2 c2 = up2(acc2[ip][jg*4+2]);
            float2 c3 = up2(acc2[ip][jg*4+3]);
            int c0i = n0 + jg*64 + tx*4;
            float4 bb = *(const float4*)(bias + c0i);
#pragma unroll
            for (int rr = 0; rr < 2; rr++) {
                int m = m0 + rbase + rr;
                float4 v;
                if (rr == 0) { v.x = c0.x + bb.x; v.y = c1.x + bb.y; v.z = c2.x + bb.z; v.w = c3.x + bb.w; }
                else         { v.x = c0.y + bb.x; v.y = c1.y + bb.y; v.z = c2.y + bb.z; v.w = c3.y + bb.w; }
                if (MODE == 3) {
                    *(float4*)(Cout + (size_t)m*Dm + c0i) = v;
                } else {
                    int b = m >> 11, n = m & 2047, h = c0i >> 6, dd = c0i & 63;
                    float* dst = (MODE == 0) ? g_q : (MODE == 1) ? g_k : g_v;
                    *(float4*)(dst + (size_t)(((b*Hh + h)*Nn + n) << 6) + dd) = v;
                }
            }
        }
    }
}

// ---------------- FAVOR+ feature maps ----------------------------------------
// Each warp handles 8 rows of one (b,h). xp = DN * (x . proj[m]), diag = 0.0625*|x|^2.
template<int ISQ>
__global__ __launch_bounds__(256) void feat_kernel() {
    const int bh = blockIdx.x;
    const int warp = threadIdx.x >> 5, lane = threadIdx.x & 31;
    const int nbase = blockIdx.y * 64 + warp * 8;
    __shared__ float shq[8][8][64];
    __shared__ float smax[8];

    const float* src = (ISQ ? g_q : g_k) + (size_t)((bh*Nn + nbase) << 6);
#pragma unroll
    for (int i = 0; i < 4; i++) {
        int fi = i*32 + lane;
        float4 v = ((const float4*)src)[fi];
        *(float4*)&shq[warp][fi >> 4][(fi & 15) * 4] = v;
    }
    __syncwarp();

    float diag[8];
#pragma unroll
    for (int r = 0; r < 8; r++) {
        float a = shq[warp][r][lane], b = shq[warp][r][lane + 32];
        float p = a*a + b*b;
#pragma unroll
        for (int o = 16; o > 0; o >>= 1) p += __shfl_xor_sync(0xffffffffu, p, o);
        diag[r] = p * 0.0625f;
    }

    // acc2[r][sp]: col-pair sp over the 8 per-thread feature columns
    u64 acc2[8][4];
#pragma unroll
    for (int r = 0; r < 8; r++)
#pragma unroll
        for (int s = 0; s < 4; s++) acc2[r][s] = 0ULL;

    const float4* pT = (const float4*)g_projT;
#pragma unroll 4
    for (int d = 0; d < 64; d++) {
        float4 p0 = pT[d*64 + lane];
        float4 p1 = pT[d*64 + 32 + lane];
        u64 pp[4] = { pk2(p0.x,p0.y), pk2(p0.z,p0.w),
                      pk2(p1.x,p1.y), pk2(p1.z,p1.w) };
#pragma unroll
        for (int r = 0; r < 8; r++) {
            u64 qd = dupf(shq[warp][r][d]);
#pragma unroll
            for (int s = 0; s < 4; s++) fma2(acc2[r][s], qd, pp[s]);
        }
    }

    if (ISQ) {
#pragma unroll
        for (int r = 0; r < 8; r++) {
            float xv[8]; float mx = -INFINITY;
#pragma unroll
            for (int s = 0; s < 4; s++) {
                float2 c = up2(acc2[r][s]);
                xv[2*s] = c.x * DN; xv[2*s+1] = c.y * DN;
                mx = fmaxf(mx, fmaxf(xv[2*s], xv[2*s+1]));
            }
#pragma unroll
            for (int o = 16; o > 0; o >>= 1) mx = fmaxf(mx, __shfl_xor_sync(0xffffffffu, mx, o));
            float base = diag[r] + mx;
            float* op = g_qp + (size_t)(bh*Nn + nbase + r) * Mf;
            float4 o0, o1;
            o0.x = RATIO*(__expf(xv[0]-base)+EPSV); o0.y = RATIO*(__expf(xv[1]-base)+EPSV);
            o0.z = RATIO*(__expf(xv[2]-base)+EPSV); o0.w = RATIO*(__expf(xv[3]-base)+EPSV);
            o1.x = RATIO*(__expf(xv[4]-base)+EPSV); o1.y = RATIO*(__expf(xv[5]-base)+EPSV);
            o1.z = RATIO*(__expf(xv[6]-base)+EPSV); o1.w = RATIO*(__expf(xv[7]-base)+EPSV);
            ((float4*)op)[lane]      = o0;
            ((float4*)op)[32 + lane] = o1;
        }
    } else {
        float wmax = -INFINITY;
#pragma unroll
        for (int r = 0; r < 8; r++) {
            float dg = diag[r];
            float xv[8];
#pragma unroll
            for (int s = 0; s < 4; s++) {
                float2 c = up2(acc2[r][s]);
                xv[2*s] = c.x * DN; xv[2*s+1] = c.y * DN;
                wmax = fmaxf(wmax, fmaxf(xv[2*s], xv[2*s+1]));
            }
            float* op = g_kp + (size_t)(bh*Nn + nbase + r) * Mf;
            float4 o0, o1;
            o0.x = xv[0]-dg; o0.y = xv[1]-dg; o0.z = xv[2]-dg; o0.w = xv[3]-dg;
            o1.x = xv[4]-dg; o1.y = xv[5]-dg; o1.z = xv[6]-dg; o1.w = xv[7]-dg;
            ((float4*)op)[lane]      = o0;
            ((float4*)op)[32 + lane] = o1;
        }
#pragma unroll
        for (int o = 16; o > 0; o >>= 1) wmax = fmaxf(wmax, __shfl_xor_sync(0xffffffffu, wmax, o));
        if (lane == 0) smax[warp] = wmax;
        __syncthreads();
        if (threadIdx.x == 0) {
            float m = smax[0];
#pragma unroll
            for (int w = 1; w < 8; w++) m = fmaxf(m, smax[w]);
            atomicMaxFloat(&g_kmax[bh], m);
        }
    }
}

// ---------------- K exp pass + k_sum -----------------------------------------
__global__ __launch_bounds__(256) void featk_exp_kernel() {
    const int bh = blockIdx.x;
    const int n0 = blockIdx.y * 256;
    const int m = threadIdx.x;
    const float kmax = g_kmax[bh];
    float s = 0.f;
    float* base = g_kp + (size_t)(bh*Nn + n0) * Mf + m;
#pragma unroll 4
    for (int i = 0; i < 256; i++) {
        float y = base[(size_t)i * Mf];
        float e = RATIO * (__expf(y - kmax) + EPSV);
        base[(size_t)i * Mf] = e;
        s += e;
    }
    atomicAdd(&g_ksum[bh*Mf + m], s);
}

// ---------------- ctx = kp^T @ v per (b,h): [256 x 64] ------------------------
__global__ __launch_bounds__(256) void ctx_kernel() {
    const int bh = blockIdx.x;
    const int nbase = blockIdx.y * 256;
    __shared__ float ks_[16][256];
    __shared__ float vs[16][64];
    const int tid = threadIdx.x;
    const int tm = tid & 31, td = tid >> 5;

    u64 acc2[8][4];
#pragma unroll
    for (int i = 0; i < 8; i++)
#pragma unroll
        for (int j = 0; j < 4; j++) acc2[i][j] = 0ULL;

    for (int t = 0; t < 16; t++) {
        int nb = nbase + t * 16;
        __syncthreads();
#pragma unroll
        for (int q = 0; q < 4; q++) {
            int t4 = tid + q*256;
            int r = t4 >> 6, c4 = (t4 & 63) * 4;
            *(float4*)&ks_[r][c4] = *(const float4*)(g_kp + (size_t)(bh*Nn + nb + r)*Mf + c4);
        }
        {
            int r = tid >> 4, c4 = (tid & 15) * 4;
            *(float4*)&vs[r][c4] = *(const float4*)(g_v + (size_t)((bh*Nn + nb + r) << 6) + c4);
        }
        __syncthreads();
#pragma unroll
        for (int i = 0; i < 16; i++) {
            float4 v0 = *(const float4*)&vs[i][td*8];
            float4 v1 = *(const float4*)&vs[i][td*8 + 4];
            u64 bp[4] = { pk2(v0.x,v0.y), pk2(v0.z,v0.w),
                          pk2(v1.x,v1.y), pk2(v1.z,v1.w) };
#pragma unroll
            for (int mi = 0; mi < 8; mi++) {
                u64 a = dupf(ks_[i][tm + 32*mi]);
#pragma unroll
                for (int dp_ = 0; dp_ < 4; dp_++) fma2(acc2[mi][dp_], a, bp[dp_]);
            }
        }
    }
#pragma unroll
    for (int mi = 0; mi < 8; mi++) {
        int m = tm + 32*mi;
#pragma unroll
        for (int dp_ = 0; dp_ < 4; dp_++) {
            float2 c = up2(acc2[mi][dp_]);
            atomicAdd(&g_ctx[(size_t)(bh*Mf + m)*HD + td*8 + dp_*2 + 0], c.x);
            atomicAdd(&g_ctx[(size_t)(bh*Mf + m)*HD + td*8 + dp_*2 + 1], c.y);
        }
    }
}

// ---------------- out = (qp @ ctx) * 1/(qp @ ksum), store [b][n][h*64+dd] -----
__global__ __launch_bounds__(256) void attn_out_kernel() {
    const int bh = blockIdx.x;
    const int n0 = blockIdx.y * 128;
    __shared__ float qs[8][128];
    __shared__ float cs[8][64];
    __shared__ float ksm[8];
    const int tid = threadIdx.x;
    const int ty = tid >> 4, tx = tid & 15;

    u64 acc2[8][2]; float dp[8];
#pragma unroll
    for (int i = 0; i < 8; i++) {
        dp[i] = 0.f;
        acc2[i][0] = 0ULL; acc2[i][1] = 0ULL;
    }

    for (int mt = 0; mt < 32; mt++) {
        int m0 = mt * 8;
        __syncthreads();
        {
            int row = tid >> 1, k4 = (tid & 1) * 4;
            float4 v = *(const float4*)(g_qp + (size_t)(bh*Nn + n0 + row)*Mf + m0 + k4);
            qs[k4+0][row] = v.x; qs[k4+1][row] = v.y;
            qs[k4+2][row] = v.z; qs[k4+3][row] = v.w;
        }
        if (tid < 128) {
            int kr = tid >> 4, c4 = (tid & 15) * 4;
            *(float4*)&cs[kr][c4] = *(const float4*)(g_ctx + (size_t)(bh*Mf + m0 + kr)*HD + c4);
        }
        if (tid < 8) ksm[tid] = g_ksum[bh*Mf + m0 + tid];
        __syncthreads();
#pragma unroll
        for (int kk = 0; kk < 8; kk++) {
            float af[8];
            *(float4*)&af[0] = *(const float4*)&qs[kk][ty*4];
            *(float4*)&af[4] = *(const float4*)&qs[kk][64 + ty*4];
            float4 b = *(const float4*)&cs[kk][tx*4];
            u64 bp[2] = { pk2(b.x,b.y), pk2(b.z,b.w) };
            float kv = ksm[kk];
#pragma unroll
            for (int i = 0; i < 8; i++) {
                dp[i] = fmaf(af[i], kv, dp[i]);
                u64 a = dupf(af[i]);
                fma2(acc2[i][0], a, bp[0]);
                fma2(acc2[i][1], a, bp[1]);
            }
        }
    }

    const int b_ = bh / Hh, h = bh % Hh;
#pragma unroll
    for (int i = 0; i < 8; i++) {
        int row = (i < 4) ? (ty*4 + i) : (64 + ty*4 + (i - 4));
        int n = n0 + row;
        float dinv = 1.0f / dp[i];
        float2 c0 = up2(acc2[i][0]);
        float2 c1 = up2(acc2[i][1]);
        float4 v;
        v.x = c0.x*dinv; v.y = c0.y*dinv;
        v.z = c1.x*dinv; v.w = c1.y*dinv;
        *(float4*)(g_attn + (size_t)(b_*Nn + n)*Dm + h*64 + tx*4) = v;
    }
}

// ---------------- launch ------------------------------------------------------
extern "C" void kernel_launch(void* const* d_in, const int* in_sizes, int n_in,
                              void* d_out, int out_size) {
    const float* x    = (const float*)d_in[0];
    const float* Wq   = (const float*)d_in[1];
    const float* bq   = (const float*)d_in[2];
    const float* Wk   = (const float*)d_in[3];
    const float* bk   = (const float*)d_in[4];
    const float* Wv   = (const float*)d_in[5];
    const float* bv   = (const float*)d_in[6];
    const float* Wo   = (const float*)d_in[7];
    const float* bo   = (const float*)d_in[8];
    const float* proj = (const float*)d_in[9];
    float* out = (float*)d_out;

    init_kernel<<<6144, 256>>>(proj);

    dim3 gg(Dm/128, (Bb*Nn)/128);           // (6, 128)
    gemm_nt<0><<<gg, 256>>>(x, Wq, bq, nullptr);
    gemm_nt<1><<<gg, 256>>>(x, Wk, bk, nullptr);
    gemm_nt<2><<<gg, 256>>>(x, Wv, bv, nullptr);

    feat_kernel<1><<<dim3(BH, Nn/64), 256>>>();   // qp
    feat_kernel<0><<<dim3(BH, Nn/64), 256>>>();   // kp raw + kmax
    featk_exp_kernel<<<dim3(BH, 8), 256>>>();     // kp exp + ksum

    ctx_kernel<<<dim3(BH, 8), 256>>>();
    attn_out_kernel<<<dim3(BH, Nn/128), 256>>>();

    gemm_nt<3><<<gg, 256>>>(nullptr, Wo, bo, out);
}

// round 6
// speedup vs baseline: 1.2311x; 1.1024x over previous
#include <cuda_runtime.h>
#include <math.h>

#define Bb 8
#define Hh 12
#define Nn 2048
#define Dm 768
#define HD 64
#define Mf 256
#define BH (Bb*Hh)

#define DN    0.35355339059327373f  /* 64^-0.25 */
#define RATIO 0.0625f               /* 256^-0.5 */
#define EPSV  1e-4f

typedef unsigned long long u64;

// ---------------- packed f32x2 helpers (FFMA2 path, sm_103a) -----------------
__device__ __forceinline__ u64 pk2(float lo, float hi) {
    u64 r; asm("mov.b64 %0, {%1, %2};" : "=l"(r) : "f"(lo), "f"(hi)); return r;
}
__device__ __forceinline__ u64 dupf(float v) {
    u64 r; asm("mov.b64 %0, {%1, %1};" : "=l"(r) : "f"(v)); return r;
}
__device__ __forceinline__ void fma2(u64& d, u64 a, u64 b) {
    asm("fma.rn.f32x2 %0, %1, %2, %0;" : "+l"(d) : "l"(a), "l"(b));
}
__device__ __forceinline__ float2 up2(u64 v) {
    float2 f; asm("mov.b64 {%0, %1}, %2;" : "=f"(f.x), "=f"(f.y) : "l"(v)); return f;
}

// ---------------- scratch (static device globals; no allocs allowed) ---------
__device__ float g_q[BH*Nn*HD];
__device__ float g_k[BH*Nn*HD];
__device__ float g_v[BH*Nn*HD];
__device__ float g_qp[BH*Nn*Mf];
__device__ float g_kp[BH*Nn*Mf];
__device__ float g_kmax[BH];
__device__ float g_ksum[BH*Mf];
__device__ float g_ctx[BH*Mf*HD];
__device__ float g_attn[Bb*Nn*Dm];
__device__ float g_projT[HD*Mf];

__device__ __forceinline__ void atomicMaxFloat(float* addr, float val) {
    if (val >= 0.f) atomicMax((int*)addr, __float_as_int(val));
    else            atomicMin((unsigned int*)addr, __float_as_uint(val));
}

// ---------------- init: zero accumulators, -inf maxes, transpose proj --------
__global__ void init_kernel(const float* __restrict__ proj) {
    int i = blockIdx.x * blockDim.x + threadIdx.x;
    int stride = gridDim.x * blockDim.x;
    for (int j = i; j < BH*Mf*HD; j += stride) g_ctx[j] = 0.f;
    if (i < BH*Mf) g_ksum[i] = 0.f;
    if (i < BH)    g_kmax[i] = -INFINITY;
    if (i < Mf*HD) {
        int m = i >> 6, d = i & 63;
        g_projT[d*Mf + m] = proj[i];
    }
}

// ---------------- GEMM core: dup-A / pack-B FFMA2 micro-kernel ---------------
// C-tile 128x128, BK=8, per-thread 8x8. acc2[r][p]: row r (0..7 mapped), col-pair p.
// B pairs come free from float4 reinterpret; A dup'd one row at a time.
struct GemmAcc { u64 a[8][4]; };

__device__ __forceinline__ void gemm_body(GemmAcc& G,
                                          const float* __restrict__ Ap,
                                          const float* __restrict__ Wp,
                                          float (*As)[128], float (*Bs)[128],
                                          int lrow, int lk4, int ty, int tx) {
#pragma unroll
    for (int r = 0; r < 8; r++)
#pragma unroll
        for (int p = 0; p < 4; p++) G.a[r][p] = 0ULL;

    float4 a_nx = *(const float4*)(Ap);
    float4 w_nx = *(const float4*)(Wp);

    for (int k0 = 0; k0 < Dm; k0 += 8) {
        __syncthreads();
        As[lk4+0][lrow] = a_nx.x; As[lk4+1][lrow] = a_nx.y;
        As[lk4+2][lrow] = a_nx.z; As[lk4+3][lrow] = a_nx.w;
        Bs[lk4+0][lrow] = w_nx.x; Bs[lk4+1][lrow] = w_nx.y;
        Bs[lk4+2][lrow] = w_nx.z; Bs[lk4+3][lrow] = w_nx.w;
        __syncthreads();
        if (k0 + 8 < Dm) {
            a_nx = *(const float4*)(Ap + k0 + 8);
            w_nx = *(const float4*)(Wp + k0 + 8);
        }
#pragma unroll
        for (int kk = 0; kk < 8; kk++) {
            float4 a0 = *(const float4*)&As[kk][ty*4];
            float4 a1 = *(const float4*)&As[kk][64 + ty*4];
            const u64* b0 = (const u64*)&Bs[kk][tx*4];
            const u64* b1 = (const u64*)&Bs[kk][64 + tx*4];
            u64 bp0 = b0[0], bp1 = b0[1], bp2 = b1[0], bp3 = b1[1];
            float ar[8] = { a0.x, a0.y, a0.z, a0.w, a1.x, a1.y, a1.z, a1.w };
#pragma unroll
            for (int r = 0; r < 8; r++) {
                u64 ad = dupf(ar[r]);
                fma2(G.a[r][0], ad, bp0);
                fma2(G.a[r][1], ad, bp1);
                fma2(G.a[r][2], ad, bp2);
                fma2(G.a[r][3], ad, bp3);
            }
        }
    }
}

// ---------------- merged QKV GEMM: sel = blockIdx.x/6 picks W/bias/dst -------
__global__ __launch_bounds__(256, 2) void gemm_qkv(const float* __restrict__ x,
                                                   const float* __restrict__ Wq, const float* __restrict__ bq,
                                                   const float* __restrict__ Wk, const float* __restrict__ bk,
                                                   const float* __restrict__ Wv, const float* __restrict__ bv) {
    __shared__ float As[8][128];
    __shared__ float Bs[8][128];
    const int tid = threadIdx.x;
    const int sel = blockIdx.x / 6;
    const float* W    = (sel == 0) ? Wq : (sel == 1) ? Wk : Wv;
    const float* bias = (sel == 0) ? bq : (sel == 1) ? bk : bv;
    float* dst        = (sel == 0) ? g_q : (sel == 1) ? g_k : g_v;
    const int n0 = (blockIdx.x % 6) * 128, m0 = blockIdx.y * 128;
    const int lrow = tid >> 1, lk4 = (tid & 1) * 4;
    const int ty = tid >> 4, tx = tid & 15;

    GemmAcc G;
    gemm_body(G, x + (size_t)(m0 + lrow)*Dm + lk4, W + (size_t)(n0 + lrow)*Dm + lk4,
              As, Bs, lrow, lk4, ty, tx);

#pragma unroll
    for (int r = 0; r < 8; r++) {
        int row = (r < 4) ? (ty*4 + r) : (64 + ty*4 + (r - 4));
        int m = m0 + row;
        int b = m >> 11, n = m & 2047;
#pragma unroll
        for (int jg = 0; jg < 2; jg++) {
            int c0 = n0 + jg*64 + tx*4;
            float4 bb = *(const float4*)(bias + c0);
            float2 cA = up2(G.a[r][2*jg]);
            float2 cB = up2(G.a[r][2*jg+1]);
            float4 v;
            v.x = cA.x + bb.x; v.y = cA.y + bb.y;
            v.z = cB.x + bb.z; v.w = cB.y + bb.w;
            int h = c0 >> 6, dd = c0 & 63;
            *(float4*)(dst + (size_t)(((b*Hh + h)*Nn + n) << 6) + dd) = v;
        }
    }
}

// ---------------- output GEMM: out = g_attn @ Wo^T + bo ----------------------
__global__ __launch_bounds__(256, 2) void gemm_out(const float* __restrict__ W,
                                                   const float* __restrict__ bias,
                                                   float* __restrict__ Cout) {
    __shared__ float As[8][128];
    __shared__ float Bs[8][128];
    const int tid = threadIdx.x;
    const int n0 = blockIdx.x * 128, m0 = blockIdx.y * 128;
    const int lrow = tid >> 1, lk4 = (tid & 1) * 4;
    const int ty = tid >> 4, tx = tid & 15;

    GemmAcc G;
    gemm_body(G, g_attn + (size_t)(m0 + lrow)*Dm + lk4, W + (size_t)(n0 + lrow)*Dm + lk4,
              As, Bs, lrow, lk4, ty, tx);

#pragma unroll
    for (int r = 0; r < 8; r++) {
        int row = (r < 4) ? (ty*4 + r) : (64 + ty*4 + (r - 4));
        int m = m0 + row;
#pragma unroll
        for (int jg = 0; jg < 2; jg++) {
            int c0 = n0 + jg*64 + tx*4;
            float4 bb = *(const float4*)(bias + c0);
            float2 cA = up2(G.a[r][2*jg]);
            float2 cB = up2(G.a[r][2*jg+1]);
            float4 v;
            v.x = cA.x + bb.x; v.y = cA.y + bb.y;
            v.z = cB.x + bb.z; v.w = cB.y + bb.w;
            *(float4*)(Cout + (size_t)m*Dm + c0) = v;
        }
    }
}

// ---------------- FAVOR+ feature maps ----------------------------------------
template<int ISQ>
__global__ __launch_bounds__(256) void feat_kernel() {
    const int bh = blockIdx.x;
    const int warp = threadIdx.x >> 5, lane = threadIdx.x & 31;
    const int nbase = blockIdx.y * 64 + warp * 8;
    __shared__ float shq[8][8][64];
    __shared__ float smax[8];

    const float* src = (ISQ ? g_q : g_k) + (size_t)((bh*Nn + nbase) << 6);
#pragma unroll
    for (int i = 0; i < 4; i++) {
        int fi = i*32 + lane;
        float4 v = ((const float4*)src)[fi];
        *(float4*)&shq[warp][fi >> 4][(fi & 15) * 4] = v;
    }
    __syncwarp();

    float diag[8];
#pragma unroll
    for (int r = 0; r < 8; r++) {
        float a = shq[warp][r][lane], b = shq[warp][r][lane + 32];
        float p = a*a + b*b;
#pragma unroll
        for (int o = 16; o > 0; o >>= 1) p += __shfl_xor_sync(0xffffffffu, p, o);
        diag[r] = p * 0.0625f;
    }

    u64 acc2[8][4];
#pragma unroll
    for (int r = 0; r < 8; r++)
#pragma unroll
        for (int s = 0; s < 4; s++) acc2[r][s] = 0ULL;

    const float4* pT = (const float4*)g_projT;
#pragma unroll 4
    for (int d = 0; d < 64; d++) {
        float4 p0 = pT[d*64 + lane];
        float4 p1 = pT[d*64 + 32 + lane];
        u64 pp0 = pk2(p0.x,p0.y), pp1 = pk2(p0.z,p0.w);
        u64 pp2 = pk2(p1.x,p1.y), pp3 = pk2(p1.z,p1.w);
#pragma unroll
        for (int r = 0; r < 8; r++) {
            u64 qd = dupf(shq[warp][r][d]);
            fma2(acc2[r][0], qd, pp0);
            fma2(acc2[r][1], qd, pp1);
            fma2(acc2[r][2], qd, pp2);
            fma2(acc2[r][3], qd, pp3);
        }
    }

    if (ISQ) {
#pragma unroll
        for (int r = 0; r < 8; r++) {
            float xv[8]; float mx = -INFINITY;
#pragma unroll
            for (int s = 0; s < 4; s++) {
                float2 c = up2(acc2[r][s]);
                xv[2*s] = c.x * DN; xv[2*s+1] = c.y * DN;
                mx = fmaxf(mx, fmaxf(xv[2*s], xv[2*s+1]));
            }
#pragma unroll
            for (int o = 16; o > 0; o >>= 1) mx = fmaxf(mx, __shfl_xor_sync(0xffffffffu, mx, o));
            float base = diag[r] + mx;
            float* op = g_qp + (size_t)(bh*Nn + nbase + r) * Mf;
            float4 o0, o1;
            o0.x = RATIO*(__expf(xv[0]-base)+EPSV); o0.y = RATIO*(__expf(xv[1]-base)+EPSV);
            o0.z = RATIO*(__expf(xv[2]-base)+EPSV); o0.w = RATIO*(__expf(xv[3]-base)+EPSV);
            o1.x = RATIO*(__expf(xv[4]-base)+EPSV); o1.y = RATIO*(__expf(xv[5]-base)+EPSV);
            o1.z = RATIO*(__expf(xv[6]-base)+EPSV); o1.w = RATIO*(__expf(xv[7]-base)+EPSV);
            ((float4*)op)[lane]      = o0;
            ((float4*)op)[32 + lane] = o1;
        }
    } else {
        float wmax = -INFINITY;
#pragma unroll
        for (int r = 0; r < 8; r++) {
            float dg = diag[r];
            float xv[8];
#pragma unroll
            for (int s = 0; s < 4; s++) {
                float2 c = up2(acc2[r][s]);
                xv[2*s] = c.x * DN; xv[2*s+1] = c.y * DN;
                wmax = fmaxf(wmax, fmaxf(xv[2*s], xv[2*s+1]));
            }
            float* op = g_kp + (size_t)(bh*Nn + nbase + r) * Mf;
            float4 o0, o1;
            o0.x = xv[0]-dg; o0.y = xv[1]-dg; o0.z = xv[2]-dg; o0.w = xv[3]-dg;
            o1.x = xv[4]-dg; o1.y = xv[5]-dg; o1.z = xv[6]-dg; o1.w = xv[7]-dg;
            ((float4*)op)[lane]      = o0;
            ((float4*)op)[32 + lane] = o1;
        }
#pragma unroll
        for (int o = 16; o > 0; o >>= 1) wmax = fmaxf(wmax, __shfl_xor_sync(0xffffffffu, wmax, o));
        if (lane == 0) smax[warp] = wmax;
        __syncthreads();
        if (threadIdx.x == 0) {
            float m = smax[0];
#pragma unroll
            for (int w = 1; w < 8; w++) m = fmaxf(m, smax[w]);
            atomicMaxFloat(&g_kmax[bh], m);
        }
    }
}

// ---------------- K exp pass + k_sum -----------------------------------------
__global__ __launch_bounds__(256) void featk_exp_kernel() {
    const int bh = blockIdx.x;
    const int n0 = blockIdx.y * 256;
    const int m = threadIdx.x;
    const float kmax = g_kmax[bh];
    float s = 0.f;
    float* base = g_kp + (size_t)(bh*Nn + n0) * Mf + m;
#pragma unroll 4
    for (int i = 0; i < 256; i++) {
        float y = base[(size_t)i * Mf];
        float e = RATIO * (__expf(y - kmax) + EPSV);
        base[(size_t)i * Mf] = e;
        s += e;
    }
    atomicAdd(&g_ksum[bh*Mf + m], s);
}

// ---------------- ctx = kp^T @ v per (b,h): [256 x 64] ------------------------
__global__ __launch_bounds__(256) void ctx_kernel() {
    const int bh = blockIdx.x;
    const int nbase = blockIdx.y * 256;
    __shared__ float ks_[16][256];
    __shared__ float vs[16][64];
    const int tid = threadIdx.x;
    const int tm = tid & 31, td = tid >> 5;

    u64 acc2[8][4];
#pragma unroll
    for (int i = 0; i < 8; i++)
#pragma unroll
        for (int j = 0; j < 4; j++) acc2[i][j] = 0ULL;

    for (int t = 0; t < 16; t++) {
        int nb = nbase + t * 16;
        __syncthreads();
#pragma unroll
        for (int q = 0; q < 4; q++) {
            int t4 = tid + q*256;
            int r = t4 >> 6, c4 = (t4 & 63) * 4;
            *(float4*)&ks_[r][c4] = *(const float4*)(g_kp + (size_t)(bh*Nn + nb + r)*Mf + c4);
        }
        {
            int r = tid >> 4, c4 = (tid & 15) * 4;
            *(float4*)&vs[r][c4] = *(const float4*)(g_v + (size_t)((bh*Nn + nb + r) << 6) + c4);
        }
        __syncthreads();
#pragma unroll
        for (int i = 0; i < 16; i++) {
            const u64* v0 = (const u64*)&vs[i][td*8];
            u64 bp0 = v0[0], bp1 = v0[1], bp2 = v0[2], bp3 = v0[3];
#pragma unroll
            for (int mi = 0; mi < 8; mi++) {
                u64 a = dupf(ks_[i][tm + 32*mi]);
                fma2(acc2[mi][0], a, bp0);
                fma2(acc2[mi][1], a, bp1);
                fma2(acc2[mi][2], a, bp2);
                fma2(acc2[mi][3], a, bp3);
            }
        }
    }
#pragma unroll
    for (int mi = 0; mi < 8; mi++) {
        int m = tm + 32*mi;
#pragma unroll
        for (int dp_ = 0; dp_ < 4; dp_++) {
            float2 c = up2(acc2[mi][dp_]);
            atomicAdd(&g_ctx[(size_t)(bh*Mf + m)*HD + td*8 + dp_*2 + 0], c.x);
            atomicAdd(&g_ctx[(size_t)(bh*Mf + m)*HD + td*8 + dp_*2 + 1], c.y);
        }
    }
}

// ---------------- out = (qp @ ctx) * 1/(qp @ ksum), store [b][n][h*64+dd] -----
__global__ __launch_bounds__(256) void attn_out_kernel() {
    const int bh = blockIdx.x;
    const int n0 = blockIdx.y * 128;
    __shared__ float qs[8][128];
    __shared__ float cs[8][64];
    __shared__ float ksm[8];
    const int tid = threadIdx.x;
    const int ty = tid >> 4, tx = tid & 15;

    u64 acc2[8][2]; float dp[8];
#pragma unroll
    for (int i = 0; i < 8; i++) {
        dp[i] = 0.f;
        acc2[i][0] = 0ULL; acc2[i][1] = 0ULL;
    }

    for (int mt = 0; mt < 32; mt++) {
        int m0 = mt * 8;
        __syncthreads();
        {
            int row = tid >> 1, k4 = (tid & 1) * 4;
            float4 v = *(const float4*)(g_qp + (size_t)(bh*Nn + n0 + row)*Mf + m0 + k4);
            qs[k4+0][row] = v.x; qs[k4+1][row] = v.y;
            qs[k4+2][row] = v.z; qs[k4+3][row] = v.w;
        }
        if (tid < 128) {
            int kr = tid >> 4, c4 = (tid & 15) * 4;
            *(float4*)&cs[kr][c4] = *(const float4*)(g_ctx + (size_t)(bh*Mf + m0 + kr)*HD + c4);
        }
        if (tid < 8) ksm[tid] = g_ksum[bh*Mf + m0 + tid];
        __syncthreads();
#pragma unroll
        for (int kk = 0; kk < 8; kk++) {
            float af[8];
            *(float4*)&af[0] = *(const float4*)&qs[kk][ty*4];
            *(float4*)&af[4] = *(const float4*)&qs[kk][64 + ty*4];
            const u64* bq_ = (const u64*)&cs[kk][tx*4];
            u64 bp0 = bq_[0], bp1 = bq_[1];
            float kv = ksm[kk];
#pragma unroll
            for (int i = 0; i < 8; i++) {
                dp[i] = fmaf(af[i], kv, dp[i]);
                u64 a = dupf(af[i]);
                fma2(acc2[i][0], a, bp0);
                fma2(acc2[i][1], a, bp1);
            }
        }
    }

    const int b_ = bh / Hh, h = bh % Hh;
#pragma unroll
    for (int i = 0; i < 8; i++) {
        int row = (i < 4) ? (ty*4 + i) : (64 + ty*4 + (i - 4));
        int n = n0 + row;
        float dinv = 1.0f / dp[i];
        float2 c0 = up2(acc2[i][0]);
        float2 c1 = up2(acc2[i][1]);
        float4 v;
        v.x = c0.x*dinv; v.y = c0.y*dinv;
        v.z = c1.x*dinv; v.w = c1.y*dinv;
        *(float4*)(g_attn + (size_t)(b_*Nn + n)*Dm + h*64 + tx*4) = v;
    }
}

// ---------------- launch ------------------------------------------------------
extern "C" void kernel_launch(void* const* d_in, const int* in_sizes, int n_in,
                              void* d_out, int out_size) {
    const float* x    = (const float*)d_in[0];
    const float* Wq   = (const float*)d_in[1];
    const float* bq   = (const float*)d_in[2];
    const float* Wk   = (const float*)d_in[3];
    const float* bk   = (const float*)d_in[4];
    const float* Wv   = (const float*)d_in[5];
    const float* bv   = (const float*)d_in[6];
    const float* Wo   = (const float*)d_in[7];
    const float* bo   = (const float*)d_in[8];
    const float* proj = (const float*)d_in[9];
    float* out = (float*)d_out;

    init_kernel<<<6144, 256>>>(proj);

    gemm_qkv<<<dim3(18, (Bb*Nn)/128), 256>>>(x, Wq, bq, Wk, bk, Wv, bv);

    feat_kernel<1><<<dim3(BH, Nn/64), 256>>>();   // qp
    feat_kernel<0><<<dim3(BH, Nn/64), 256>>>();   // kp raw + kmax
    featk_exp_kernel<<<dim3(BH, 8), 256>>>();     // kp exp + ksum

    ctx_kernel<<<dim3(BH, 8), 256>>>();
    attn_out_kernel<<<dim3(BH, Nn/128), 256>>>();

    gemm_out<<<dim3(Dm/128, (Bb*Nn)/128), 256>>>(Wo, bo, out);
}

// round 13
// speedup vs baseline: 1.9900x; 1.6164x over previous
#include <cuda_runtime.h>
#include <cuda_bf16.h>
#include <math.h>
#include <stdint.h>

#define Bb 8
#define Hh 12
#define Nn 2048
#define Dm 768
#define HD 64
#define Mf 256
#define BH (Bb*Hh)

#define DN    0.35355339059327373f  /* 64^-0.25 */
#define RATIO 0.0625f               /* 256^-0.5 */
#define EPSV  1e-4f

typedef unsigned long long u64;

// ---------------- packed f32x2 helpers (FFMA2 path, sm_103a) -----------------
__device__ __forceinline__ u64 pk2(float lo, float hi) {
    u64 r; asm("mov.b64 %0, {%1, %2};" : "=l"(r) : "f"(lo), "f"(hi)); return r;
}
__device__ __forceinline__ u64 dupf(float v) {
    u64 r; asm("mov.b64 %0, {%1, %1};" : "=l"(r) : "f"(v)); return r;
}
__device__ __forceinline__ void fma2(u64& d, u64 a, u64 b) {
    asm("fma.rn.f32x2 %0, %1, %2, %0;" : "+l"(d) : "l"(a), "l"(b));
}
__device__ __forceinline__ float2 up2(u64 v) {
    float2 f; asm("mov.b64 {%0, %1}, %2;" : "=f"(f.x), "=f"(f.y) : "l"(v)); return f;
}

// ---------------- scratch (static device globals; no allocs allowed) ---------
__device__ float g_q[BH*Nn*HD];
__device__ float g_k[BH*Nn*HD];
__device__ float g_v[BH*Nn*HD];
__device__ float g_qp[BH*Nn*Mf];
__device__ float g_kp[BH*Nn*Mf];
__device__ float g_kmax[BH];
__device__ float g_ksum[BH*Mf];
__device__ float g_ctx[BH*Mf*HD];
__device__ float g_attn[Bb*Nn*Dm];
__device__ float g_projT[HD*Mf];
// bf16 hi/lo splits for tensor-core GEMMs
__device__ __align__(16) __nv_bfloat16 g_xhi[Bb*Nn*Dm];
__device__ __align__(16) __nv_bfloat16 g_xlo[Bb*Nn*Dm];
__device__ __align__(16) __nv_bfloat16 g_wh[4*Dm*Dm];   // slots: Wq, Wk, Wv, Wo
__device__ __align__(16) __nv_bfloat16 g_wl[4*Dm*Dm];

__device__ __forceinline__ void atomicMaxFloat(float* addr, float val) {
    if (val >= 0.f) atomicMax((int*)addr, __float_as_int(val));
    else            atomicMin((unsigned int*)addr, __float_as_uint(val));
}

// ---------------- baseline-PTX tensor helpers (compute_103-safe) -------------
__device__ __forceinline__ uint32_t s2u(const void* p) {
    uint32_t a;
    asm("{ .reg .u64 t; cvta.to.shared.u64 t, %1; cvt.u32.u64 %0, t; }" : "=r"(a) : "l"(p));
    return a;
}
__device__ __forceinline__ void cpa16(uint32_t s, const void* g) {
    asm volatile("cp.async.cg.shared.global [%0], [%1], 16;" :: "r"(s), "l"(g));
}
__device__ __forceinline__ void cpcommit() {
    asm volatile("cp.async.commit_group;" ::: "memory");
}
template<int N> __device__ __forceinline__ void cpwait() {
    asm volatile("cp.async.wait_group %0;" :: "n"(N) : "memory");
}
__device__ __forceinline__ void ldm4(uint32_t a, uint32_t r[4]) {
    asm volatile("ldmatrix.sync.aligned.m8n8.x4.shared.b16 {%0,%1,%2,%3}, [%4];"
                 : "=r"(r[0]), "=r"(r[1]), "=r"(r[2]), "=r"(r[3]) : "r"(a));
}
__device__ __forceinline__ void mma16816(float* c, const uint32_t* a, const uint32_t* b) {
    asm volatile(
        "mma.sync.aligned.m16n8k16.row.col.f32.bf16.bf16.f32 "
        "{%0,%1,%2,%3}, {%4,%5,%6,%7}, {%8,%9}, {%0,%1,%2,%3};"
        : "+f"(c[0]), "+f"(c[1]), "+f"(c[2]), "+f"(c[3])
        : "r"(a[0]), "r"(a[1]), "r"(a[2]), "r"(a[3]), "r"(b[0]), "r"(b[1]));
}

// ---------------- init: zero accumulators, -inf maxes, transpose proj --------
__global__ void init_kernel(const float* __restrict__ proj) {
    int i = blockIdx.x * blockDim.x + threadIdx.x;
    int stride = gridDim.x * blockDim.x;
    for (int j = i; j < BH*Mf*HD; j += stride) g_ctx[j] = 0.f;
    if (i < BH*Mf) g_ksum[i] = 0.f;
    if (i < BH)    g_kmax[i] = -INFINITY;
    if (i < Mf*HD) {
        int m = i >> 6, d = i & 63;
        g_projT[d*Mf + m] = proj[i];
    }
}

// ---------------- bf16 hi/lo split kernels ------------------------------------
__device__ __forceinline__ void split1(float a, __nv_bfloat16& h, __nv_bfloat16& l) {
    h = __float2bfloat16(a);
    l = __float2bfloat16(a - __bfloat162float(h));
}
__global__ void split_x_kernel(const float* __restrict__ src) {
    int i = blockIdx.x * blockDim.x + threadIdx.x;   // over Bb*Nn*Dm
    float a = src[i];
    split1(a, g_xhi[i], g_xlo[i]);
}
__global__ void split_attn_kernel() {
    int i = blockIdx.x * blockDim.x + threadIdx.x;
    float a = g_attn[i];
    split1(a, g_xhi[i], g_xlo[i]);
}
__global__ void split_w_kernel(const float* __restrict__ src, int slot) {
    int i = blockIdx.x * blockDim.x + threadIdx.x;   // over Dm*Dm
    float a = src[i];
    size_t o = (size_t)slot * Dm * Dm + i;
    split1(a, g_wh[o], g_wl[o]);
}

// ---------------- mma.sync bf16x3 GEMM: C = A @ W^T + bias -------------------
// Tile 128x128, 8 warps (2x4), warp tile 64x32, Kc=32 double-buffered cp.async.
// smem per stage: Ahi(8K) Alo(8K) Bhi(8K) Blo(8K) = 32KB; 2 stages = 64KB.
// Swizzle: 16B chunk c within 64B row -> c ^ ((row>>1)&3): conflict-free ldmatrix.
// Pipeline: cpwait+syncthreads THEN prefetch other stage (prevents WAR race).
#define STG   32768
#define R_ALO 8192
#define R_BHI 16384
#define R_BLO 24576
#define GSMEM (2*STG)
#define NKC   24

template<int QKV>
__global__ __launch_bounds__(256) void gemm_mma(const float* __restrict__ b0_,
                                                const float* __restrict__ b1_,
                                                const float* __restrict__ b2_,
                                                float* __restrict__ Cout) {
    extern __shared__ char smem[];
    const uint32_t sb = s2u(smem);
    const int tid = threadIdx.x;

    int sel, nblk;
    if (QKV) { sel = blockIdx.x / 6; nblk = blockIdx.x % 6; }
    else     { sel = 3;              nblk = blockIdx.x; }
    const int m0 = blockIdx.y * 128, n0 = nblk * 128;
    const __nv_bfloat16* Wh = g_wh + (size_t)sel * Dm * Dm;
    const __nv_bfloat16* Wl = g_wl + (size_t)sel * Dm * Dm;

    const int lane = tid & 31, warp = tid >> 5;
    const int wm = warp >> 2, wn = warp & 3;
    const int li = lane & 7, mid = lane >> 3;

    // per-thread fill coords (2 chunks per region)
    const int frow = tid >> 2, fc = tid & 3;

    float acc[4][4][4];
#pragma unroll
    for (int i = 0; i < 4; i++)
#pragma unroll
        for (int j = 0; j < 4; j++)
#pragma unroll
            for (int k = 0; k < 4; k++) acc[i][j][k] = 0.f;

    // ldmatrix row/swizzle precompute
    int rA[4], sA[4];
#pragma unroll
    for (int mf = 0; mf < 4; mf++) {
        rA[mf] = wm*64 + mf*16 + li + ((mid & 1) << 3);
        sA[mf] = (rA[mf] >> 1) & 3;
    }
    const int cAadd = mid >> 1;
    int rB[2], sB[2];
#pragma unroll
    for (int nt = 0; nt < 2; nt++) {
        rB[nt] = wn*32 + nt*16 + li + ((mid >> 1) << 3);
        sB[nt] = (rB[nt] >> 1) & 3;
    }
    const int cBadd = mid & 1;

    // ---- stage fill lambda ----
    auto fill = [&](int s, int kc) {
        const int k0 = kc * 32;
        const uint32_t st = sb + s * STG;
#pragma unroll
        for (int i = 0; i < 2; i++) {
            int row = frow + i*64;
            uint32_t off = row*64 + ((fc ^ ((row >> 1) & 3)) << 4);
            size_t aoff = (size_t)(m0 + row) * Dm + k0 + fc*8;
            size_t boff = (size_t)(n0 + row) * Dm + k0 + fc*8;
            cpa16(st + off,         g_xhi + aoff);
            cpa16(st + R_ALO + off, g_xlo + aoff);
            cpa16(st + R_BHI + off, Wh + boff);
            cpa16(st + R_BLO + off, Wl + boff);
        }
        cpcommit();
    };

    fill(0, 0);
    for (int kc = 0; kc < NKC; kc++) {
        // wait for this stage's data, barrier, THEN prefetch into the other
        // stage (all warps have finished reading it: they passed this barrier
        // after computing on it last iteration).
        cpwait<0>();
        __syncthreads();
        if (kc + 1 < NKC) fill((kc + 1) & 1, kc + 1);

        const uint32_t st = sb + (kc & 1) * STG;
#pragma unroll
        for (int ks = 0; ks < 2; ks++) {
            const int cb = 2*ks;
            uint32_t offA[4];
#pragma unroll
            for (int mf = 0; mf < 4; mf++)
                offA[mf] = rA[mf]*64 + (((cb + cAadd) ^ sA[mf]) << 4);
            uint32_t offB[2];
#pragma unroll
            for (int nt = 0; nt < 2; nt++)
                offB[nt] = rB[nt]*64 + (((cb + cBadd) ^ sB[nt]) << 4);

            // B hi/lo fragments
            uint32_t bh[4][2], bl[4][2];
#pragma unroll
            for (int nt = 0; nt < 2; nt++) {
                uint32_t r[4];
                ldm4(st + R_BHI + offB[nt], r);
                bh[2*nt][0] = r[0]; bh[2*nt][1] = r[1];
                bh[2*nt+1][0] = r[2]; bh[2*nt+1][1] = r[3];
                ldm4(st + R_BLO + offB[nt], r);
                bl[2*nt][0] = r[0]; bl[2*nt][1] = r[1];
                bl[2*nt+1][0] = r[2]; bl[2*nt+1][1] = r[3];
            }
            // A hi fragments; hi*hi + hi*lo
            uint32_t af[4][4];
#pragma unroll
            for (int mf = 0; mf < 4; mf++) ldm4(st + offA[mf], af[mf]);
#pragma unroll
            for (int mf = 0; mf < 4; mf++)
#pragma unroll
                for (int nf = 0; nf < 4; nf++) {
                    mma16816(acc[mf][nf], af[mf], bh[nf]);
                    mma16816(acc[mf][nf], af[mf], bl[nf]);
                }
            // A lo (reuse af regs); lo*hi
#pragma unroll
            for (int mf = 0; mf < 4; mf++) ldm4(st + R_ALO + offA[mf], af[mf]);
#pragma unroll
            for (int mf = 0; mf < 4; mf++)
#pragma unroll
                for (int nf = 0; nf < 4; nf++)
                    mma16816(acc[mf][nf], af[mf], bh[nf]);
        }
    }

    // ---- epilogue: bias + (scatter | plain) store -----------------------------
    const float* bias = QKV ? ((sel == 0) ? b0_ : (sel == 1) ? b1_ : b2_) : b0_;
    float* dst = QKV ? ((sel == 0) ? g_q : (sel == 1) ? g_k : g_v) : Cout;
#pragma unroll
    for (int mf = 0; mf < 4; mf++)
#pragma unroll
        for (int nf = 0; nf < 4; nf++) {
            int cnG = n0 + wn*32 + nf*8 + 2*(lane & 3);
            float2 bb = *(const float2*)(bias + cnG);
#pragma unroll
            for (int h2 = 0; h2 < 2; h2++) {
                int m = m0 + wm*64 + mf*16 + (lane >> 2) + 8*h2;
                float2 v;
                v.x = acc[mf][nf][2*h2]   + bb.x;
                v.y = acc[mf][nf][2*h2+1] + bb.y;
                if (QKV) {
                    int b = m >> 11, n = m & 2047, hh = cnG >> 6, dd = cnG & 63;
                    *(float2*)(dst + ((size_t)((b*Hh + hh)*Nn + n) << 6) + dd) = v;
                } else {
                    *(float2*)(dst + (size_t)m * Dm + cnG) = v;
                }
            }
        }
}

// ---------------- FAVOR+ feature maps ----------------------------------------
template<int ISQ>
__global__ __launch_bounds__(256, 2) void feat_kernel() {
    const int bh = blockIdx.x;
    const int warp = threadIdx.x >> 5, lane = threadIdx.x & 31;
    const int nbase = blockIdx.y * 64 + warp * 8;
    __shared__ float shq[8][8][64];
    __shared__ float smax[8];

    const float* src = (ISQ ? g_q : g_k) + (size_t)((bh*Nn + nbase) << 6);
#pragma unroll
    for (int i = 0; i < 4; i++) {
        int fi = i*32 + lane;
        float4 v = ((const float4*)src)[fi];
        *(float4*)&shq[warp][fi >> 4][(fi & 15) * 4] = v;
    }
    __syncwarp();

    float diag[8];
#pragma unroll
    for (int r = 0; r < 8; r++) {
        float a = shq[warp][r][lane], b = shq[warp][r][lane + 32];
        float p = a*a + b*b;
#pragma unroll
        for (int o = 16; o > 0; o >>= 1) p += __shfl_xor_sync(0xffffffffu, p, o);
        diag[r] = p * 0.0625f;
    }

    u64 acc2[8][4];
#pragma unroll
    for (int r = 0; r < 8; r++)
#pragma unroll
        for (int s = 0; s < 4; s++) acc2[r][s] = 0ULL;

    const float4* pT = (const float4*)g_projT;
#pragma unroll 4
    for (int d = 0; d < 64; d++) {
        float4 p0 = pT[d*64 + lane];
        float4 p1 = pT[d*64 + 32 + lane];
        u64 pp0 = pk2(p0.x,p0.y), pp1 = pk2(p0.z,p0.w);
        u64 pp2 = pk2(p1.x,p1.y), pp3 = pk2(p1.z,p1.w);
#pragma unroll
        for (int r = 0; r < 8; r++) {
            u64 qd = dupf(shq[warp][r][d]);
            fma2(acc2[r][0], qd, pp0);
            fma2(acc2[r][1], qd, pp1);
            fma2(acc2[r][2], qd, pp2);
            fma2(acc2[r][3], qd, pp3);
        }
    }

    if (ISQ) {
#pragma unroll
        for (int r = 0; r < 8; r++) {
            float xv[8]; float mx = -INFINITY;
#pragma unroll
            for (int s = 0; s < 4; s++) {
                float2 c = up2(acc2[r][s]);
                xv[2*s] = c.x * DN; xv[2*s+1] = c.y * DN;
                mx = fmaxf(mx, fmaxf(xv[2*s], xv[2*s+1]));
            }
#pragma unroll
            for (int o = 16; o > 0; o >>= 1) mx = fmaxf(mx, __shfl_xor_sync(0xffffffffu, mx, o));
            float base = diag[r] + mx;
            float* op = g_qp + (size_t)(bh*Nn + nbase + r) * Mf;
            float4 o0, o1;
            o0.x = RATIO*(__expf(xv[0]-base)+EPSV); o0.y = RATIO*(__expf(xv[1]-base)+EPSV);
            o0.z = RATIO*(__expf(xv[2]-base)+EPSV); o0.w = RATIO*(__expf(xv[3]-base)+EPSV);
            o1.x = RATIO*(__expf(xv[4]-base)+EPSV); o1.y = RATIO*(__expf(xv[5]-base)+EPSV);
            o1.z = RATIO*(__expf(xv[6]-base)+EPSV); o1.w = RATIO*(__expf(xv[7]-base)+EPSV);
            ((float4*)op)[lane]      = o0;
            ((float4*)op)[32 + lane] = o1;
        }
    } else {
        float wmax = -INFINITY;
#pragma unroll
        for (int r = 0; r < 8; r++) {
            float dg = diag[r];
            float xv[8];
#pragma unroll
            for (int s = 0; s < 4; s++) {
                float2 c = up2(acc2[r][s]);
                xv[2*s] = c.x * DN; xv[2*s+1] = c.y * DN;
                wmax = fmaxf(wmax, fmaxf(xv[2*s], xv[2*s+1]));
            }
            float* op = g_kp + (size_t)(bh*Nn + nbase + r) * Mf;
            float4 o0, o1;
            o0.x = xv[0]-dg; o0.y = xv[1]-dg; o0.z = xv[2]-dg; o0.w = xv[3]-dg;
            o1.x = xv[4]-dg; o1.y = xv[5]-dg; o1.z = xv[6]-dg; o1.w = xv[7]-dg;
            ((float4*)op)[lane]      = o0;
            ((float4*)op)[32 + lane] = o1;
        }
#pragma unroll
        for (int o = 16; o > 0; o >>= 1) wmax = fmaxf(wmax, __shfl_xor_sync(0xffffffffu, wmax, o));
        if (lane == 0) smax[warp] = wmax;
        __syncthreads();
        if (threadIdx.x == 0) {
            float m = smax[0];
#pragma unroll
            for (int w = 1; w < 8; w++) m = fmaxf(m, smax[w]);
            atomicMaxFloat(&g_kmax[bh], m);
        }
    }
}

// ---------------- K exp pass + k_sum -----------------------------------------
__global__ __launch_bounds__(256) void featk_exp_kernel() {
    const int bh = blockIdx.x;
    const int n0 = blockIdx.y * 256;
    const int m = threadIdx.x;
    const float kmax = g_kmax[bh];
    float s = 0.f;
    float* base = g_kp + (size_t)(bh*Nn + n0) * Mf + m;
#pragma unroll 4
    for (int i = 0; i < 256; i++) {
        float y = base[(size_t)i * Mf];
        float e = RATIO * (__expf(y - kmax) + EPSV);
        base[(size_t)i * Mf] = e;
        s += e;
    }
    atomicAdd(&g_ksum[bh*Mf + m], s);
}

// ---------------- ctx = kp^T @ v per (b,h): [256 x 64] ------------------------
__global__ __launch_bounds__(256) void ctx_kernel() {
    const int bh = blockIdx.x;
    const int nbase = blockIdx.y * 256;
    __shared__ float ks_[16][256];
    __shared__ float vs[16][64];
    const int tid = threadIdx.x;
    const int tm = tid & 31, td = tid >> 5;

    u64 acc2[8][4];
#pragma unroll
    for (int i = 0; i < 8; i++)
#pragma unroll
        for (int j = 0; j < 4; j++) acc2[i][j] = 0ULL;

    for (int t = 0; t < 16; t++) {
        int nb = nbase + t * 16;
        __syncthreads();
#pragma unroll
        for (int q = 0; q < 4; q++) {
            int t4 = tid + q*256;
            int r = t4 >> 6, c4 = (t4 & 63) * 4;
            *(float4*)&ks_[r][c4] = *(const float4*)(g_kp + (size_t)(bh*Nn + nb + r)*Mf + c4);
        }
        {
            int r = tid >> 4, c4 = (tid & 15) * 4;
            *(float4*)&vs[r][c4] = *(const float4*)(g_v + (size_t)((bh*Nn + nb + r) << 6) + c4);
        }
        __syncthreads();
#pragma unroll
        for (int i = 0; i < 16; i++) {
            const u64* v0 = (const u64*)&vs[i][td*8];
            u64 bp0 = v0[0], bp1 = v0[1], bp2 = v0[2], bp3 = v0[3];
#pragma unroll
            for (int mi = 0; mi < 8; mi++) {
                u64 a = dupf(ks_[i][tm + 32*mi]);
                fma2(acc2[mi][0], a, bp0);
                fma2(acc2[mi][1], a, bp1);
                fma2(acc2[mi][2], a, bp2);
                fma2(acc2[mi][3], a, bp3);
            }
        }
    }
#pragma unroll
    for (int mi = 0; mi < 8; mi++) {
        int m = tm + 32*mi;
#pragma unroll
        for (int dp_ = 0; dp_ < 4; dp_++) {
            float2 c = up2(acc2[mi][dp_]);
            atomicAdd(&g_ctx[(size_t)(bh*Mf + m)*HD + td*8 + dp_*2 + 0], c.x);
            atomicAdd(&g_ctx[(size_t)(bh*Mf + m)*HD + td*8 + dp_*2 + 1], c.y);
        }
    }
}

// ---------------- out = (qp @ ctx) * 1/(qp @ ksum), store [b][n][h*64+dd] -----
__global__ __launch_bounds__(256) void attn_out_kernel() {
    const int bh = blockIdx.x;
    const int n0 = blockIdx.y * 128;
    __shared__ float qs[8][128];
    __shared__ float cs[8][64];
    __shared__ float ksm[8];
    const int tid = threadIdx.x;
    const int ty = tid >> 4, tx = tid & 15;

    u64 acc2[8][2]; float dp[8];
#pragma unroll
    for (int i = 0; i < 8; i++) {
        dp[i] = 0.f;
        acc2[i][0] = 0ULL; acc2[i][1] = 0ULL;
    }

    for (int mt = 0; mt < 32; mt++) {
        int m0 = mt * 8;
        __syncthreads();
        {
            int row = tid >> 1, k4 = (tid & 1) * 4;
            float4 v = *(const float4*)(g_qp + (size_t)(bh*Nn + n0 + row)*Mf + m0 + k4);
            qs[k4+0][row] = v.x; qs[k4+1][row] = v.y;
            qs[k4+2][row] = v.z; qs[k4+3][row] = v.w;
        }
        if (tid < 128) {
            int kr = tid >> 4, c4 = (tid & 15) * 4;
            *(float4*)&cs[kr][c4] = *(const float4*)(g_ctx + (size_t)(bh*Mf + m0 + kr)*HD + c4);
        }
        if (tid < 8) ksm[tid] = g_ksum[bh*Mf + m0 + tid];
        __syncthreads();
#pragma unroll
        for (int kk = 0; kk < 8; kk++) {
            float af[8];
            *(float4*)&af[0] = *(const float4*)&qs[kk][ty*4];
            *(float4*)&af[4] = *(const float4*)&qs[kk][64 + ty*4];
            const u64* bq_ = (const u64*)&cs[kk][tx*4];
            u64 bp0 = bq_[0], bp1 = bq_[1];
            float kv = ksm[kk];
#pragma unroll
            for (int i = 0; i < 8; i++) {
                dp[i] = fmaf(af[i], kv, dp[i]);
                u64 a = dupf(af[i]);
                fma2(acc2[i][0], a, bp0);
                fma2(acc2[i][1], a, bp1);
            }
        }
    }

    const int b_ = bh / Hh, h = bh % Hh;
#pragma unroll
    for (int i = 0; i < 8; i++) {
        int row = (i < 4) ? (ty*4 + i) : (64 + ty*4 + (i - 4));
        int n = n0 + row;
        float dinv = 1.0f / dp[i];
        float2 c0 = up2(acc2[i][0]);
        float2 c1 = up2(acc2[i][1]);
        float4 v;
        v.x = c0.x*dinv; v.y = c0.y*dinv;
        v.z = c1.x*dinv; v.w = c1.y*dinv;
        *(float4*)(g_attn + (size_t)(b_*Nn + n)*Dm + h*64 + tx*4) = v;
    }
}

// ---------------- launch ------------------------------------------------------
extern "C" void kernel_launch(void* const* d_in, const int* in_sizes, int n_in,
                              void* d_out, int out_size) {
    const float* x    = (const float*)d_in[0];
    const float* Wq   = (const float*)d_in[1];
    const float* bq   = (const float*)d_in[2];
    const float* Wk   = (const float*)d_in[3];
    const float* bk   = (const float*)d_in[4];
    const float* Wv   = (const float*)d_in[5];
    const float* bv   = (const float*)d_in[6];
    const float* Wo   = (const float*)d_in[7];
    const float* bo   = (const float*)d_in[8];
    const float* proj = (const float*)d_in[9];
    float* out = (float*)d_out;

    cudaFuncSetAttribute(gemm_mma<1>, cudaFuncAttributeMaxDynamicSharedMemorySize, GSMEM);
    cudaFuncSetAttribute(gemm_mma<0>, cudaFuncAttributeMaxDynamicSharedMemorySize, GSMEM);

    init_kernel<<<6144, 256>>>(proj);
    split_x_kernel<<<(Bb*Nn*Dm)/256, 256>>>(x);
    split_w_kernel<<<(Dm*Dm)/256, 256>>>(Wq, 0);
    split_w_kernel<<<(Dm*Dm)/256, 256>>>(Wk, 1);
    split_w_kernel<<<(Dm*Dm)/256, 256>>>(Wv, 2);
    split_w_kernel<<<(Dm*Dm)/256, 256>>>(Wo, 3);

    gemm_mma<1><<<dim3(18, (Bb*Nn)/128), 256, GSMEM>>>(bq, bk, bv, nullptr);

    feat_kernel<1><<<dim3(BH, Nn/64), 256>>>();   // qp
    feat_kernel<0><<<dim3(BH, Nn/64), 256>>>();   // kp raw + kmax
    featk_exp_kernel<<<dim3(BH, 8), 256>>>();     // kp exp + ksum

    ctx_kernel<<<dim3(BH, 8), 256>>>();
    attn_out_kernel<<<dim3(BH, Nn/128), 256>>>();

    split_attn_kernel<<<(Bb*Nn*Dm)/256, 256>>>();
    gemm_mma<0><<<dim3(6, (Bb*Nn)/128), 256, GSMEM>>>(bo, bo, bo, out);
}

// round 16
// speedup vs baseline: 2.3244x; 1.1680x over previous
#include <cuda_runtime.h>
#include <cuda_bf16.h>
#include <math.h>
#include <stdint.h>

#define Bb 8
#define Hh 12
#define Nn 2048
#define Dm 768
#define HD 64
#define Mf 256
#define BH (Bb*Hh)

#define DN    0.35355339059327373f  /* 64^-0.25 */
#define RATIO 0.0625f               /* 256^-0.5 */
#define EPSV  1e-4f

typedef unsigned long long u64;

// ---------------- packed f32x2 helpers (FFMA2 path, sm_103a) -----------------
__device__ __forceinline__ u64 pk2(float lo, float hi) {
    u64 r; asm("mov.b64 %0, {%1, %2};" : "=l"(r) : "f"(lo), "f"(hi)); return r;
}
__device__ __forceinline__ u64 dupf(float v) {
    u64 r; asm("mov.b64 %0, {%1, %1};" : "=l"(r) : "f"(v)); return r;
}
__device__ __forceinline__ void fma2(u64& d, u64 a, u64 b) {
    asm("fma.rn.f32x2 %0, %1, %2, %0;" : "+l"(d) : "l"(a), "l"(b));
}
__device__ __forceinline__ float2 up2(u64 v) {
    float2 f; asm("mov.b64 {%0, %1}, %2;" : "=f"(f.x), "=f"(f.y) : "l"(v)); return f;
}

// ---------------- scratch (static device globals; no allocs allowed) ---------
__device__ float g_q[BH*Nn*HD];
__device__ float g_k[BH*Nn*HD];
__device__ float g_v[BH*Nn*HD];
__device__ float g_qp[BH*Nn*Mf];
__device__ float g_kp[BH*Nn*Mf];
__device__ float g_kmax[BH];
__device__ float g_ksum[BH*Mf];
__device__ float g_ctx[BH*Mf*HD];
__device__ float g_attn[Bb*Nn*Dm];
// bf16 hi/lo splits for tensor-core GEMMs
__device__ __align__(16) __nv_bfloat16 g_xhi[Bb*Nn*Dm];
__device__ __align__(16) __nv_bfloat16 g_xlo[Bb*Nn*Dm];
__device__ __align__(16) __nv_bfloat16 g_wh[4*Dm*Dm];   // slots: Wq, Wk, Wv, Wo
__device__ __align__(16) __nv_bfloat16 g_wl[4*Dm*Dm];
__device__ __align__(16) __nv_bfloat16 g_ph[Mf*HD];     // proj hi/lo [m][d]
__device__ __align__(16) __nv_bfloat16 g_pl[Mf*HD];

__device__ __forceinline__ void atomicMaxFloat(float* addr, float val) {
    if (val >= 0.f) atomicMax((int*)addr, __float_as_int(val));
    else            atomicMin((unsigned int*)addr, __float_as_uint(val));
}

// ---------------- baseline-PTX tensor helpers (compute_103-safe) -------------
__device__ __forceinline__ uint32_t s2u(const void* p) {
    uint32_t a;
    asm("{ .reg .u64 t; cvta.to.shared.u64 t, %1; cvt.u32.u64 %0, t; }" : "=r"(a) : "l"(p));
    return a;
}
__device__ __forceinline__ void cpa16(uint32_t s, const void* g) {
    asm volatile("cp.async.cg.shared.global [%0], [%1], 16;" :: "r"(s), "l"(g));
}
__device__ __forceinline__ void cpcommit() {
    asm volatile("cp.async.commit_group;" ::: "memory");
}
template<int N> __device__ __forceinline__ void cpwait() {
    asm volatile("cp.async.wait_group %0;" :: "n"(N) : "memory");
}
__device__ __forceinline__ void ldm4(uint32_t a, uint32_t r[4]) {
    asm volatile("ldmatrix.sync.aligned.m8n8.x4.shared.b16 {%0,%1,%2,%3}, [%4];"
                 : "=r"(r[0]), "=r"(r[1]), "=r"(r[2]), "=r"(r[3]) : "r"(a));
}
__device__ __forceinline__ void mma16816(float* c, const uint32_t* a, const uint32_t* b) {
    asm volatile(
        "mma.sync.aligned.m16n8k16.row.col.f32.bf16.bf16.f32 "
        "{%0,%1,%2,%3}, {%4,%5,%6,%7}, {%8,%9}, {%0,%1,%2,%3};"
        : "+f"(c[0]), "+f"(c[1]), "+f"(c[2]), "+f"(c[3])
        : "r"(a[0]), "r"(a[1]), "r"(a[2]), "r"(a[3]), "r"(b[0]), "r"(b[1]));
}

// ---------------- init: zero accumulators, -inf maxes, split proj ------------
__global__ void init_kernel(const float* __restrict__ proj) {
    int i = blockIdx.x * blockDim.x + threadIdx.x;
    int stride = gridDim.x * blockDim.x;
    for (int j = i; j < BH*Mf*HD; j += stride) g_ctx[j] = 0.f;
    if (i < BH*Mf) g_ksum[i] = 0.f;
    if (i < BH)    g_kmax[i] = -INFINITY;
    if (i < Mf*HD) {
        float a = proj[i];
        __nv_bfloat16 h = __float2bfloat16(a);
        g_ph[i] = h;
        g_pl[i] = __float2bfloat16(a - __bfloat162float(h));
    }
}

// ---------------- bf16 hi/lo split kernels ------------------------------------
__device__ __forceinline__ void split1(float a, __nv_bfloat16& h, __nv_bfloat16& l) {
    h = __float2bfloat16(a);
    l = __float2bfloat16(a - __bfloat162float(h));
}
__global__ void split_x_kernel(const float* __restrict__ src) {
    int i = blockIdx.x * blockDim.x + threadIdx.x;
    float a = src[i];
    split1(a, g_xhi[i], g_xlo[i]);
}
__global__ void split_attn_kernel() {
    int i = blockIdx.x * blockDim.x + threadIdx.x;
    float a = g_attn[i];
    split1(a, g_xhi[i], g_xlo[i]);
}
__global__ void split_w_kernel(const float* __restrict__ src, int slot) {
    int i = blockIdx.x * blockDim.x + threadIdx.x;
    float a = src[i];
    size_t o = (size_t)slot * Dm * Dm + i;
    split1(a, g_wh[o], g_wl[o]);
}

// ---------------- mma.sync bf16x3 GEMM: C = A @ W^T + bias -------------------
#define STG   32768
#define R_ALO 8192
#define R_BHI 16384
#define R_BLO 24576
#define GSMEM (2*STG)
#define NKC   24

template<int QKV>
__global__ __launch_bounds__(256) void gemm_mma(const float* __restrict__ b0_,
                                                const float* __restrict__ b1_,
                                                const float* __restrict__ b2_,
                                                float* __restrict__ Cout) {
    extern __shared__ char smem[];
    const uint32_t sb = s2u(smem);
    const int tid = threadIdx.x;

    int sel, nblk;
    if (QKV) { sel = blockIdx.x / 6; nblk = blockIdx.x % 6; }
    else     { sel = 3;              nblk = blockIdx.x; }
    const int m0 = blockIdx.y * 128, n0 = nblk * 128;
    const __nv_bfloat16* Wh = g_wh + (size_t)sel * Dm * Dm;
    const __nv_bfloat16* Wl = g_wl + (size_t)sel * Dm * Dm;

    const int lane = tid & 31, warp = tid >> 5;
    const int wm = warp >> 2, wn = warp & 3;
    const int li = lane & 7, mid = lane >> 3;
    const int frow = tid >> 2, fc = tid & 3;

    float acc[4][4][4];
#pragma unroll
    for (int i = 0; i < 4; i++)
#pragma unroll
        for (int j = 0; j < 4; j++)
#pragma unroll
            for (int k = 0; k < 4; k++) acc[i][j][k] = 0.f;

    int rA[4], sA[4];
#pragma unroll
    for (int mf = 0; mf < 4; mf++) {
        rA[mf] = wm*64 + mf*16 + li + ((mid & 1) << 3);
        sA[mf] = (rA[mf] >> 1) & 3;
    }
    const int cAadd = mid >> 1;
    int rB[2], sB[2];
#pragma unroll
    for (int nt = 0; nt < 2; nt++) {
        rB[nt] = wn*32 + nt*16 + li + ((mid >> 1) << 3);
        sB[nt] = (rB[nt] >> 1) & 3;
    }
    const int cBadd = mid & 1;

    auto fill = [&](int s, int kc) {
        const int k0 = kc * 32;
        const uint32_t st = sb + s * STG;
#pragma unroll
        for (int i = 0; i < 2; i++) {
            int row = frow + i*64;
            uint32_t off = row*64 + ((fc ^ ((row >> 1) & 3)) << 4);
            size_t aoff = (size_t)(m0 + row) * Dm + k0 + fc*8;
            size_t boff = (size_t)(n0 + row) * Dm + k0 + fc*8;
            cpa16(st + off,         g_xhi + aoff);
            cpa16(st + R_ALO + off, g_xlo + aoff);
            cpa16(st + R_BHI + off, Wh + boff);
            cpa16(st + R_BLO + off, Wl + boff);
        }
        cpcommit();
    };

    fill(0, 0);
    for (int kc = 0; kc < NKC; kc++) {
        cpwait<0>();
        __syncthreads();
        if (kc + 1 < NKC) fill((kc + 1) & 1, kc + 1);

        const uint32_t st = sb + (kc & 1) * STG;
#pragma unroll
        for (int ks = 0; ks < 2; ks++) {
            const int cb = 2*ks;
            uint32_t offA[4];
#pragma unroll
            for (int mf = 0; mf < 4; mf++)
                offA[mf] = rA[mf]*64 + (((cb + cAadd) ^ sA[mf]) << 4);
            uint32_t offB[2];
#pragma unroll
            for (int nt = 0; nt < 2; nt++)
                offB[nt] = rB[nt]*64 + (((cb + cBadd) ^ sB[nt]) << 4);

            uint32_t bh[4][2], bl[4][2];
#pragma unroll
            for (int nt = 0; nt < 2; nt++) {
                uint32_t r[4];
                ldm4(st + R_BHI + offB[nt], r);
                bh[2*nt][0] = r[0]; bh[2*nt][1] = r[1];
                bh[2*nt+1][0] = r[2]; bh[2*nt+1][1] = r[3];
                ldm4(st + R_BLO + offB[nt], r);
                bl[2*nt][0] = r[0]; bl[2*nt][1] = r[1];
                bl[2*nt+1][0] = r[2]; bl[2*nt+1][1] = r[3];
            }
            uint32_t af[4][4];
#pragma unroll
            for (int mf = 0; mf < 4; mf++) ldm4(st + offA[mf], af[mf]);
#pragma unroll
            for (int mf = 0; mf < 4; mf++)
#pragma unroll
                for (int nf = 0; nf < 4; nf++) {
                    mma16816(acc[mf][nf], af[mf], bh[nf]);
                    mma16816(acc[mf][nf], af[mf], bl[nf]);
                }
#pragma unroll
            for (int mf = 0; mf < 4; mf++) ldm4(st + R_ALO + offA[mf], af[mf]);
#pragma unroll
            for (int mf = 0; mf < 4; mf++)
#pragma unroll
                for (int nf = 0; nf < 4; nf++)
                    mma16816(acc[mf][nf], af[mf], bh[nf]);
        }
    }

    const float* bias = QKV ? ((sel == 0) ? b0_ : (sel == 1) ? b1_ : b2_) : b0_;
    float* dst = QKV ? ((sel == 0) ? g_q : (sel == 1) ? g_k : g_v) : Cout;
#pragma unroll
    for (int mf = 0; mf < 4; mf++)
#pragma unroll
        for (int nf = 0; nf < 4; nf++) {
            int cnG = n0 + wn*32 + nf*8 + 2*(lane & 3);
            float2 bb = *(const float2*)(bias + cnG);
#pragma unroll
            for (int h2 = 0; h2 < 2; h2++) {
                int m = m0 + wm*64 + mf*16 + (lane >> 2) + 8*h2;
                float2 v;
                v.x = acc[mf][nf][2*h2]   + bb.x;
                v.y = acc[mf][nf][2*h2+1] + bb.y;
                if (QKV) {
                    int b = m >> 11, n = m & 2047, hh = cnG >> 6, dd = cnG & 63;
                    *(float2*)(dst + ((size_t)((b*Hh + hh)*Nn + n) << 6) + dd) = v;
                } else {
                    *(float2*)(dst + (size_t)m * Dm + cnG) = v;
                }
            }
        }
}

// ---------------- FAVOR+ feature maps via mma.sync bf16x3 --------------------
// Per CTA: 64 rows (n) x 256 cols (features), K=64. 8 warps as 2(rows)x4(cols).
// A = q*DN split hi/lo in-kernel (128B rows, chunk swizzle c^(row&7));
// B = proj hi/lo from g_ph/g_pl. diag reconstructed from hi+lo.
#define F_AHI 0
#define F_ALO 8192
#define F_BHI 16384
#define F_BLO 49152
#define F_DIAG 81920
#define F_RMAX 82432
#define FSMEM  (F_RMAX + 64*4*4)

template<int ISQ>
__global__ __launch_bounds__(256) void feat_mma() {
    extern __shared__ char smem[];
    const uint32_t sb = s2u(smem);
    float* s_diag = (float*)(smem + F_DIAG);
    float* s_rmax = (float*)(smem + F_RMAX);
    const int tid = threadIdx.x;
    const int bh = blockIdx.x;
    const int nbase = blockIdx.y * 64;
    const int lane = tid & 31, warp = tid >> 5;
    const int wm = warp >> 2, wn = warp & 3;       // wm: 32-row half, wn: 64-col quarter
    const int li = lane & 7, mid = lane >> 3;

    // ---- load + scale + split q (64x64), compute diag ----
    {
        const float* src = (ISQ ? g_q : g_k) + (size_t)((bh*Nn + nbase) << 6);
        const int row = tid >> 2;          // 0..63
        const int cp = tid & 3;
        float dsum = 0.f;
#pragma unroll
        for (int i = 0; i < 2; i++) {
            int c = cp*2 + i;              // chunk 0..7 (8 cols each)
            const float4* qr = (const float4*)(src + row*64 + c*8);
            float4 f0 = qr[0], f1 = qr[1];
            float t[8] = { f0.x*DN, f0.y*DN, f0.z*DN, f0.w*DN,
                           f1.x*DN, f1.y*DN, f1.z*DN, f1.w*DN };
            struct { __nv_bfloat16 v[8]; } hi8, lo8;
#pragma unroll
            for (int j = 0; j < 8; j++) {
                dsum += t[j]*t[j];
                hi8.v[j] = __float2bfloat16(t[j]);
                lo8.v[j] = __float2bfloat16(t[j] - __bfloat162float(hi8.v[j]));
            }
            uint32_t off = row*128 + ((c ^ (row & 7)) << 4);
            *(uint4*)(smem + F_AHI + off) = *(uint4*)&hi8;
            *(uint4*)(smem + F_ALO + off) = *(uint4*)&lo8;
        }
        dsum += __shfl_xor_sync(0xffffffffu, dsum, 1);
        dsum += __shfl_xor_sync(0xffffffffu, dsum, 2);
        if ((tid & 3) == 0) s_diag[row] = 0.5f * dsum;
    }
    // ---- load proj hi/lo (256x64) ----
#pragma unroll
    for (int i = 0; i < 8; i++) {
        int idx = tid + 256*i;
        int rp = idx >> 3, c = idx & 7;
        uint32_t off = rp*128 + ((c ^ (rp & 7)) << 4);
        *(uint4*)(smem + F_BHI + off) = *(const uint4*)(g_ph + rp*64 + c*8);
        *(uint4*)(smem + F_BLO + off) = *(const uint4*)(g_pl + rp*64 + c*8);
    }
    __syncthreads();

    // ---- mma: warp tile 32 rows x 64 cols, K=64 ----
    float acc[2][8][4];
#pragma unroll
    for (int i = 0; i < 2; i++)
#pragma unroll
        for (int j = 0; j < 8; j++)
#pragma unroll
            for (int k = 0; k < 4; k++) acc[i][j][k] = 0.f;

    int rA[2];
#pragma unroll
    for (int mf = 0; mf < 2; mf++) rA[mf] = wm*32 + mf*16 + li + ((mid & 1) << 3);
    const int cAadd = mid >> 1;
    int rB[4];
#pragma unroll
    for (int nt = 0; nt < 4; nt++) rB[nt] = wn*64 + nt*16 + li + ((mid >> 1) << 3);
    const int cBadd = mid & 1;

#pragma unroll
    for (int ks = 0; ks < 4; ks++) {
        const int cb = 2*ks;
        uint32_t bhf[8][2], blf[8][2];
#pragma unroll
        for (int nt = 0; nt < 4; nt++) {
            uint32_t off = rB[nt]*128 + (((cb + cBadd) ^ (rB[nt] & 7)) << 4);
            uint32_t r[4];
            ldm4(sb + F_BHI + off, r);
            bhf[2*nt][0] = r[0]; bhf[2*nt][1] = r[1];
            bhf[2*nt+1][0] = r[2]; bhf[2*nt+1][1] = r[3];
            ldm4(sb + F_BLO + off, r);
            blf[2*nt][0] = r[0]; blf[2*nt][1] = r[1];
            blf[2*nt+1][0] = r[2]; blf[2*nt+1][1] = r[3];
        }
        uint32_t af[2][4];
        uint32_t offA[2];
#pragma unroll
        for (int mf = 0; mf < 2; mf++) {
            offA[mf] = rA[mf]*128 + (((cb + cAadd) ^ (rA[mf] & 7)) << 4);
            ldm4(sb + F_AHI + offA[mf], af[mf]);
        }
#pragma unroll
        for (int mf = 0; mf < 2; mf++)
#pragma unroll
            for (int nf = 0; nf < 8; nf++) {
                mma16816(acc[mf][nf], af[mf], bhf[nf]);
                mma16816(acc[mf][nf], af[mf], blf[nf]);
            }
#pragma unroll
        for (int mf = 0; mf < 2; mf++) ldm4(sb + F_ALO + offA[mf], af[mf]);
#pragma unroll
        for (int mf = 0; mf < 2; mf++)
#pragma unroll
            for (int nf = 0; nf < 8; nf++)
                mma16816(acc[mf][nf], af[mf], bhf[nf]);
    }

    // ---- epilogue ----
    // value at: row r = wm*32 + mf*16 + (lane>>2) + 8*h, col = wn*64 + nf*8 + 2*(lane&3) + e
    if (ISQ) {
#pragma unroll
        for (int mf = 0; mf < 2; mf++)
#pragma unroll
            for (int h = 0; h < 2; h++) {
                float m = -INFINITY;
#pragma unroll
                for (int nf = 0; nf < 8; nf++)
                    m = fmaxf(m, fmaxf(acc[mf][nf][2*h], acc[mf][nf][2*h+1]));
                m = fmaxf(m, __shfl_xor_sync(0xffffffffu, m, 1));
                m = fmaxf(m, __shfl_xor_sync(0xffffffffu, m, 2));
                if ((lane & 3) == 0) {
                    int r = wm*32 + mf*16 + (lane >> 2) + 8*h;
                    s_rmax[r*4 + wn] = m;
                }
            }
        __syncthreads();
#pragma unroll
        for (int mf = 0; mf < 2; mf++)
#pragma unroll
            for (int h = 0; h < 2; h++) {
                int r = wm*32 + mf*16 + (lane >> 2) + 8*h;
                float mx = fmaxf(fmaxf(s_rmax[r*4+0], s_rmax[r*4+1]),
                                 fmaxf(s_rmax[r*4+2], s_rmax[r*4+3]));
                float base = s_diag[r] + mx;
                float* op = g_qp + (size_t)(bh*Nn + nbase + r)*Mf + wn*64 + 2*(lane & 3);
#pragma unroll
                for (int nf = 0; nf < 8; nf++) {
                    float2 v;
                    v.x = RATIO*(__expf(acc[mf][nf][2*h]   - base) + EPSV);
                    v.y = RATIO*(__expf(acc[mf][nf][2*h+1] - base) + EPSV);
                    *(float2*)(op + nf*8) = v;
                }
            }
    } else {
        float wmax = -INFINITY;
#pragma unroll
        for (int mf = 0; mf < 2; mf++)
#pragma unroll
            for (int h = 0; h < 2; h++) {
                int r = wm*32 + mf*16 + (lane >> 2) + 8*h;
                float dg = s_diag[r];
                float* op = g_kp + (size_t)(bh*Nn + nbase + r)*Mf + wn*64 + 2*(lane & 3);
#pragma unroll
                for (int nf = 0; nf < 8; nf++) {
                    float a0 = acc[mf][nf][2*h], a1 = acc[mf][nf][2*h+1];
                    wmax = fmaxf(wmax, fmaxf(a0, a1));
                    float2 v; v.x = a0 - dg; v.y = a1 - dg;
                    *(float2*)(op + nf*8) = v;
                }
            }
#pragma unroll
        for (int o = 16; o > 0; o >>= 1)
            wmax = fmaxf(wmax, __shfl_xor_sync(0xffffffffu, wmax, o));
        __shared__ float s_wm[8];
        if (lane == 0) s_wm[warp] = wmax;
        __syncthreads();
        if (tid == 0) {
            float m = s_wm[0];
#pragma unroll
            for (int w = 1; w < 8; w++) m = fmaxf(m, s_wm[w]);
            atomicMaxFloat(&g_kmax[bh], m);
        }
    }
}

// ---------------- ctx = exp(kp)^T @ v per (b,h), fused exp + ksum ------------
__global__ __launch_bounds__(256) void ctx_kernel() {
    const int bh = blockIdx.x;
    const int nbase = blockIdx.y * 256;
    __shared__ float ks_[16][256];
    __shared__ float vs[16][64];
    const int tid = threadIdx.x;
    const int tm = tid & 31, td = tid >> 5;
    const float kmax = g_kmax[bh];

    float ksum_p[4] = {0.f, 0.f, 0.f, 0.f};

    u64 acc2[8][4];
#pragma unroll
    for (int i = 0; i < 8; i++)
#pragma unroll
        for (int j = 0; j < 4; j++) acc2[i][j] = 0ULL;

    for (int t = 0; t < 16; t++) {
        int nb = nbase + t * 16;
        __syncthreads();
#pragma unroll
        for (int q = 0; q < 4; q++) {
            int t4 = tid + q*256;
            int r = t4 >> 6, c4 = (t4 & 63) * 4;
            float4 v = *(const float4*)(g_kp + (size_t)(bh*Nn + nb + r)*Mf + c4);
            v.x = RATIO*(__expf(v.x - kmax) + EPSV);
            v.y = RATIO*(__expf(v.y - kmax) + EPSV);
            v.z = RATIO*(__expf(v.z - kmax) + EPSV);
            v.w = RATIO*(__expf(v.w - kmax) + EPSV);
            ksum_p[0] += v.x; ksum_p[1] += v.y; ksum_p[2] += v.z; ksum_p[3] += v.w;
            *(float4*)&ks_[r][c4] = v;
        }
        {
            int r = tid >> 4, c4 = (tid & 15) * 4;
            *(float4*)&vs[r][c4] = *(const float4*)(g_v + (size_t)((bh*Nn + nb + r) << 6) + c4);
        }
        __syncthreads();
#pragma unroll
        for (int i = 0; i < 16; i++) {
            const u64* v0 = (const u64*)&vs[i][td*8];
            u64 bp0 = v0[0], bp1 = v0[1], bp2 = v0[2], bp3 = v0[3];
#pragma unroll
            for (int mi = 0; mi < 8; mi++) {
                u64 a = dupf(ks_[i][tm + 32*mi]);
                fma2(acc2[mi][0], a, bp0);
                fma2(acc2[mi][1], a, bp1);
                fma2(acc2[mi][2], a, bp2);
                fma2(acc2[mi][3], a, bp3);
            }
        }
    }
#pragma unroll
    for (int j = 0; j < 4; j++)
        atomicAdd(&g_ksum[bh*Mf + (tid & 63)*4 + j], ksum_p[j]);
#pragma unroll
    for (int mi = 0; mi < 8; mi++) {
        int m = tm + 32*mi;
#pragma unroll
        for (int dp_ = 0; dp_ < 4; dp_++) {
            float2 c = up2(acc2[mi][dp_]);
            atomicAdd(&g_ctx[(size_t)(bh*Mf + m)*HD + td*8 + dp_*2 + 0], c.x);
            atomicAdd(&g_ctx[(size_t)(bh*Mf + m)*HD + td*8 + dp_*2 + 1], c.y);
        }
    }
}

// ---------------- out = (qp @ ctx) * 1/(qp @ ksum), store [b][n][h*64+dd] -----
__global__ __launch_bounds__(256) void attn_out_kernel() {
    const int bh = blockIdx.x;
    const int n0 = blockIdx.y * 128;
    __shared__ float qs[8][128];
    __shared__ float cs[8][64];
    __shared__ float ksm[8];
    const int tid = threadIdx.x;
    const int ty = tid >> 4, tx = tid & 15;

    u64 acc2[8][2]; float dp[8];
#pragma unroll
    for (int i = 0; i < 8; i++) {
        dp[i] = 0.f;
        acc2[i][0] = 0ULL; acc2[i][1] = 0ULL;
    }

    for (int mt = 0; mt < 32; mt++) {
        int m0 = mt * 8;
        __syncthreads();
        {
            int row = tid >> 1, k4 = (tid & 1) * 4;
            float4 v = *(const float4*)(g_qp + (size_t)(bh*Nn + n0 + row)*Mf + m0 + k4);
            qs[k4+0][row] = v.x; qs[k4+1][row] = v.y;
            qs[k4+2][row] = v.z; qs[k4+3][row] = v.w;
        }
        if (tid < 128) {
            int kr = tid >> 4, c4 = (tid & 15) * 4;
            *(float4*)&cs[kr][c4] = *(const float4*)(g_ctx + (size_t)(bh*Mf + m0 + kr)*HD + c4);
        }
        if (tid < 8) ksm[tid] = g_ksum[bh*Mf + m0 + tid];
        __syncthreads();
#pragma unroll
        for (int kk = 0; kk < 8; kk++) {
            float af[8];
            *(float4*)&af[0] = *(const float4*)&qs[kk][ty*4];
            *(float4*)&af[4] = *(const float4*)&qs[kk][64 + ty*4];
            const u64* bq_ = (const u64*)&cs[kk][tx*4];
            u64 bp0 = bq_[0], bp1 = bq_[1];
            float kv = ksm[kk];
#pragma unroll
            for (int i = 0; i < 8; i++) {
                dp[i] = fmaf(af[i], kv, dp[i]);
                u64 a = dupf(af[i]);
                fma2(acc2[i][0], a, bp0);
                fma2(acc2[i][1], a, bp1);
            }
        }
    }

    const int b_ = bh / Hh, h = bh % Hh;
#pragma unroll
    for (int i = 0; i < 8; i++) {
        int row = (i < 4) ? (ty*4 + i) : (64 + ty*4 + (i - 4));
        int n = n0 + row;
        float dinv = 1.0f / dp[i];
        float2 c0 = up2(acc2[i][0]);
        float2 c1 = up2(acc2[i][1]);
        float4 v;
        v.x = c0.x*dinv; v.y = c0.y*dinv;
        v.z = c1.x*dinv; v.w = c1.y*dinv;
        *(float4*)(g_attn + (size_t)(b_*Nn + n)*Dm + h*64 + tx*4) = v;
    }
}

// ---------------- launch ------------------------------------------------------
extern "C" void kernel_launch(void* const* d_in, const int* in_sizes, int n_in,
                              void* d_out, int out_size) {
    const float* x    = (const float*)d_in[0];
    const float* Wq   = (const float*)d_in[1];
    const float* bq   = (const float*)d_in[2];
    const float* Wk   = (const float*)d_in[3];
    const float* bk   = (const float*)d_in[4];
    const float* Wv   = (const float*)d_in[5];
    const float* bv   = (const float*)d_in[6];
    const float* Wo   = (const float*)d_in[7];
    const float* bo   = (const float*)d_in[8];
    const float* proj = (const float*)d_in[9];
    float* out = (float*)d_out;

    cudaFuncSetAttribute(gemm_mma<1>, cudaFuncAttributeMaxDynamicSharedMemorySize, GSMEM);
    cudaFuncSetAttribute(gemm_mma<0>, cudaFuncAttributeMaxDynamicSharedMemorySize, GSMEM);
    cudaFuncSetAttribute(feat_mma<1>, cudaFuncAttributeMaxDynamicSharedMemorySize, FSMEM);
    cudaFuncSetAttribute(feat_mma<0>, cudaFuncAttributeMaxDynamicSharedMemorySize, FSMEM);

    init_kernel<<<6144, 256>>>(proj);
    split_x_kernel<<<(Bb*Nn*Dm)/256, 256>>>(x);
    split_w_kernel<<<(Dm*Dm)/256, 256>>>(Wq, 0);
    split_w_kernel<<<(Dm*Dm)/256, 256>>>(Wk, 1);
    split_w_kernel<<<(Dm*Dm)/256, 256>>>(Wv, 2);
    split_w_kernel<<<(Dm*Dm)/256, 256>>>(Wo, 3);

    gemm_mma<1><<<dim3(18, (Bb*Nn)/128), 256, GSMEM>>>(bq, bk, bv, nullptr);

    feat_mma<1><<<dim3(BH, Nn/64), 256, FSMEM>>>();   // qp (exp'd)
    feat_mma<0><<<dim3(BH, Nn/64), 256, FSMEM>>>();   // kp raw + kmax

    ctx_kernel<<<dim3(BH, 8), 256>>>();               // fused exp + ksum + ctx
    attn_out_kernel<<<dim3(BH, Nn/128), 256>>>();

    split_attn_kernel<<<(Bb*Nn*Dm)/256, 256>>>();
    gemm_mma<0><<<dim3(6, (Bb*Nn)/128), 256, GSMEM>>>(bo, bo, bo, out);
}